// round 4
// baseline (speedup 1.0000x reference)
#include <cuda_runtime.h>
#include <cstdint>
#include <math.h>

#define JAX_PARTITIONABLE 1

#define Bb 16
#define Ss 512
#define Dd 768
#define Kc 8192
#define Hh 8
#define Ll 6
#define FFd 2048
#define NTOK 8192
#define DH 96
#define NEGB (-1e9f)

// ---------------- scratch (device globals; no allocation allowed) ----------------
__device__ float g_mem  [NTOK * Dd];        // z_e (cross-attn memory)
__device__ float g_h    [NTOK * Dd];        // residual stream
__device__ float g_tmp  [NTOK * Dd];        // pre-LN residual sum
__device__ float g_attno[NTOK * Dd];        // attention output (pre-proj)
__device__ float g_qkv  [NTOK * 3 * Dd];
__device__ float g_ffbuf[NTOK * FFd];
__device__ float g_scores[(size_t)Bb * Hh * Ss * Ss];
__device__ float g_dist [(size_t)NTOK * Kc];
__device__ float g_xnorm[NTOK];
__device__ float g_cnorm[Kc];
__device__ int   g_pad  [NTOK];
__device__ int   g_enc  [NTOK];

// ---------------- reductions ----------------
__device__ __forceinline__ float blockReduceSum256(float v, float* sb) {
    int tid = threadIdx.x;
    #pragma unroll
    for (int o = 16; o > 0; o >>= 1) v += __shfl_down_sync(0xffffffffu, v, o);
    if ((tid & 31) == 0) sb[tid >> 5] = v;
    __syncthreads();
    float s = 0.f;
    if (tid < 32) {
        s = (tid < (int)(blockDim.x >> 5)) ? sb[tid] : 0.f;
        #pragma unroll
        for (int o = 16; o > 0; o >>= 1) s += __shfl_down_sync(0xffffffffu, s, o);
        if (tid == 0) sb[0] = s;
    }
    __syncthreads();
    float r = sb[0];
    __syncthreads();
    return r;
}

__device__ __forceinline__ float blockReduceMax(float v, float* sb) {
    int tid = threadIdx.x;
    #pragma unroll
    for (int o = 16; o > 0; o >>= 1) v = fmaxf(v, __shfl_down_sync(0xffffffffu, v, o));
    if ((tid & 31) == 0) sb[tid >> 5] = v;
    __syncthreads();
    float s = -3.4e38f;
    if (tid < 32) {
        s = (tid < (int)(blockDim.x >> 5)) ? sb[tid] : -3.4e38f;
        #pragma unroll
        for (int o = 16; o > 0; o >>= 1) s = fmaxf(s, __shfl_down_sync(0xffffffffu, s, o));
        if (tid == 0) sb[0] = s;
    }
    __syncthreads();
    float r = sb[0];
    __syncthreads();
    return r;
}

// ---------------- row stats ----------------
__global__ void __launch_bounds__(256) rowstat_x(const float* __restrict__ x) {
    __shared__ float sb[32];
    int row = blockIdx.x, tid = threadIdx.x;
    float v[3];
    #pragma unroll
    for (int i = 0; i < 3; i++) v[i] = x[(size_t)row * Dd + tid + i * 256];
    float ss = v[0]*v[0] + v[1]*v[1] + v[2]*v[2];
    ss = blockReduceSum256(ss, sb);
    int pad = (sqrtf(ss) <= 1e-6f) ? 1 : 0;
    if (tid == 0) { g_pad[row] = pad; g_xnorm[row] = pad ? 0.f : ss; }
    #pragma unroll
    for (int i = 0; i < 3; i++)
        g_mem[(size_t)row * Dd + tid + i * 256] = pad ? 0.f : v[i];
}

__global__ void __launch_bounds__(256) rowstat_cb(const float* __restrict__ cb) {
    __shared__ float sb[32];
    int row = blockIdx.x, tid = threadIdx.x;
    float ss = 0.f;
    #pragma unroll
    for (int i = 0; i < 3; i++) {
        float v = cb[(size_t)row * Dd + tid + i * 256];
        ss += v * v;
    }
    ss = blockReduceSum256(ss, sb);
    if (tid == 0) g_cnorm[row] = ss;
}

// ---------------- generic NT SGEMM: C = epi(sum_k A[m,k]*W[n,k]) ----------------
// mode 0: +bias   mode 1: relu(+bias)   mode 2: +bias+resid   mode 3: (rn[m]+cn[n]) - 2*acc
__global__ void __launch_bounds__(256) sgemm_nt(
    const float* __restrict__ A, int lda,
    const float* __restrict__ W, int ldw,
    const float* __restrict__ bias,
    const float* __restrict__ resid, int ldr,
    const float* __restrict__ rnorm, const float* __restrict__ cnorm,
    float* __restrict__ C, int ldc, int K, int mode)
{
    __shared__ float As[16][132];
    __shared__ float Ws[16][132];
    const int bm = blockIdx.y * 128, bn = blockIdx.x * 128;
    const int tid = threadIdx.x;
    const int tx = tid & 15, ty = tid >> 4;
    float acc[8][8];
    #pragma unroll
    for (int i = 0; i < 8; i++)
        #pragma unroll
        for (int j = 0; j < 8; j++) acc[i][j] = 0.f;

    for (int k0 = 0; k0 < K; k0 += 16) {
        #pragma unroll
        for (int u = 0; u < 2; u++) {
            int f = tid + u * 256;
            int row = f >> 2;
            int c4 = (f & 3) << 2;
            float4 a = *(const float4*)(A + (size_t)(bm + row) * lda + k0 + c4);
            As[c4 + 0][row] = a.x; As[c4 + 1][row] = a.y;
            As[c4 + 2][row] = a.z; As[c4 + 3][row] = a.w;
            float4 w = *(const float4*)(W + (size_t)(bn + row) * ldw + k0 + c4);
            Ws[c4 + 0][row] = w.x; Ws[c4 + 1][row] = w.y;
            Ws[c4 + 2][row] = w.z; Ws[c4 + 3][row] = w.w;
        }
        __syncthreads();
        #pragma unroll
        for (int kk = 0; kk < 16; kk++) {
            float a[8], b[8];
            *(float4*)(a)     = *(const float4*)&As[kk][ty * 8];
            *(float4*)(a + 4) = *(const float4*)&As[kk][ty * 8 + 4];
            *(float4*)(b)     = *(const float4*)&Ws[kk][tx * 8];
            *(float4*)(b + 4) = *(const float4*)&Ws[kk][tx * 8 + 4];
            #pragma unroll
            for (int i = 0; i < 8; i++)
                #pragma unroll
                for (int j = 0; j < 8; j++)
                    acc[i][j] = fmaf(a[i], b[j], acc[i][j]);
        }
        __syncthreads();
    }

    #pragma unroll
    for (int i = 0; i < 8; i++) {
        int row = bm + ty * 8 + i;
        #pragma unroll
        for (int jj = 0; jj < 8; jj += 4) {
            int col = bn + tx * 8 + jj;
            float4 v = make_float4(acc[i][jj], acc[i][jj+1], acc[i][jj+2], acc[i][jj+3]);
            if (mode == 3) {
                float xn = rnorm[row];
                v.x = (xn + cnorm[col + 0]) - 2.f * v.x;
                v.y = (xn + cnorm[col + 1]) - 2.f * v.y;
                v.z = (xn + cnorm[col + 2]) - 2.f * v.z;
                v.w = (xn + cnorm[col + 3]) - 2.f * v.w;
            } else {
                if (bias) {
                    float4 bv = *(const float4*)(bias + col);
                    v.x += bv.x; v.y += bv.y; v.z += bv.z; v.w += bv.w;
                }
                if (mode == 2) {
                    float4 r = *(const float4*)(resid + (size_t)row * ldr + col);
                    v.x += r.x; v.y += r.y; v.z += r.z; v.w += r.w;
                }
                if (mode == 1) {
                    v.x = fmaxf(v.x, 0.f); v.y = fmaxf(v.y, 0.f);
                    v.z = fmaxf(v.z, 0.f); v.w = fmaxf(v.w, 0.f);
                }
            }
            *(float4*)(C + (size_t)row * ldc + col) = v;
        }
    }
}

// ---------------- attention: scores ----------------
__global__ void __launch_bounds__(256) attn_scores(int causal) {
    __shared__ float Qs[32][68];
    __shared__ float Ks[32][68];
    int kt = blockIdx.x, qt = blockIdx.y, bh = blockIdx.z;
    int b = bh >> 3, h = bh & 7;
    const float* __restrict__ Qb = g_qkv + (size_t)b * Ss * 3 * Dd + h * DH;
    const float* __restrict__ Kb = Qb + Dd;
    int tid = threadIdx.x, tx = tid & 15, ty = tid >> 4;
    float acc[4][4];
    #pragma unroll
    for (int i = 0; i < 4; i++)
        #pragma unroll
        for (int j = 0; j < 4; j++) acc[i][j] = 0.f;

    for (int k0 = 0; k0 < DH; k0 += 32) {
        #pragma unroll
        for (int u = 0; u < 2; u++) {
            int f = tid + u * 256;
            int row = f >> 3;
            int c4 = (f & 7) << 2;
            float4 q = *(const float4*)(Qb + (size_t)(qt * 64 + row) * (3 * Dd) + k0 + c4);
            Qs[c4 + 0][row] = q.x; Qs[c4 + 1][row] = q.y;
            Qs[c4 + 2][row] = q.z; Qs[c4 + 3][row] = q.w;
            float4 kv = *(const float4*)(Kb + (size_t)(kt * 64 + row) * (3 * Dd) + k0 + c4);
            Ks[c4 + 0][row] = kv.x; Ks[c4 + 1][row] = kv.y;
            Ks[c4 + 2][row] = kv.z; Ks[c4 + 3][row] = kv.w;
        }
        __syncthreads();
        #pragma unroll
        for (int kk = 0; kk < 32; kk++) {
            float a[4], bfr[4];
            *(float4*)a   = *(const float4*)&Qs[kk][ty * 4];
            *(float4*)bfr = *(const float4*)&Ks[kk][tx * 4];
            #pragma unroll
            for (int i = 0; i < 4; i++)
                #pragma unroll
                for (int j = 0; j < 4; j++)
                    acc[i][j] = fmaf(a[i], bfr[j], acc[i][j]);
        }
        __syncthreads();
    }

    const float scale = 9.797958971132712f;  // np.float32(np.sqrt(96))
    #pragma unroll
    for (int i = 0; i < 4; i++) {
        int q = qt * 64 + ty * 4 + i;
        float4 v;
        float* pv = &v.x;
        #pragma unroll
        for (int j = 0; j < 4; j++) {
            int k = kt * 64 + tx * 4 + j;
            float s = acc[i][j] / scale;
            if (causal && q > k) s += NEGB;
            if (g_pad[b * Ss + k]) s += NEGB;
            pv[j] = s;
        }
        *(float4*)(g_scores + ((size_t)bh * Ss + q) * Ss + kt * 64 + tx * 4) = v;
    }
}

// ---------------- softmax over rows of 512 (vectorized) ----------------
__global__ void __launch_bounds__(128) softmax512() {
    __shared__ float sb[32];
    float* p = g_scores + (size_t)blockIdx.x * Ss;
    int tid = threadIdx.x;
    float4 v = *(const float4*)(p + tid * 4);
    float m = fmaxf(fmaxf(v.x, v.y), fmaxf(v.z, v.w));
    m = blockReduceMax(m, sb);
    float4 e;
    e.x = expf(v.x - m); e.y = expf(v.y - m);
    e.z = expf(v.z - m); e.w = expf(v.w - m);
    float s = e.x + e.y + e.z + e.w;
    s = blockReduceSum256(s, sb);
    float inv = 1.0f / s;
    e.x *= inv; e.y *= inv; e.z *= inv; e.w *= inv;
    *(float4*)(p + tid * 4) = e;
}

// ---------------- attention: P @ V ----------------
__global__ void __launch_bounds__(256) attn_av() {
    __shared__ float Ps[16][68];
    __shared__ float Vs[16][96];
    int qt = blockIdx.x, bh = blockIdx.y;
    int b = bh >> 3, h = bh & 7;
    const float* __restrict__ P = g_scores + (size_t)bh * Ss * Ss + (size_t)qt * 64 * Ss;
    const float* __restrict__ Vb = g_qkv + (size_t)b * Ss * 3 * Dd + 2 * Dd + h * DH;
    int tid = threadIdx.x, tx = tid & 15, ty = tid >> 4;
    float acc[4][6];
    #pragma unroll
    for (int i = 0; i < 4; i++)
        #pragma unroll
        for (int j = 0; j < 6; j++) acc[i][j] = 0.f;

    for (int k0 = 0; k0 < Ss; k0 += 16) {
        {
            int row = tid >> 2;
            int c4 = (tid & 3) << 2;
            float4 pv = *(const float4*)(P + (size_t)row * Ss + k0 + c4);
            Ps[c4 + 0][row] = pv.x; Ps[c4 + 1][row] = pv.y;
            Ps[c4 + 2][row] = pv.z; Ps[c4 + 3][row] = pv.w;
        }
        #pragma unroll
        for (int u = 0; u < 6; u++) {
            int f = tid + u * 256;
            int r = f / 96, c = f - r * 96;
            Vs[r][c] = Vb[(size_t)(k0 + r) * (3 * Dd) + c];
        }
        __syncthreads();
        #pragma unroll
        for (int kk = 0; kk < 16; kk++) {
            float a[4];
            *(float4*)a = *(const float4*)&Ps[kk][ty * 4];
            float bf[6];
            #pragma unroll
            for (int j = 0; j < 6; j++) bf[j] = Vs[kk][tx * 6 + j];
            #pragma unroll
            for (int i = 0; i < 4; i++)
                #pragma unroll
                for (int j = 0; j < 6; j++)
                    acc[i][j] = fmaf(a[i], bf[j], acc[i][j]);
        }
        __syncthreads();
    }
    #pragma unroll
    for (int i = 0; i < 4; i++) {
        int q = qt * 64 + ty * 4 + i;
        #pragma unroll
        for (int j = 0; j < 6; j++)
            g_attno[(size_t)(b * Ss + q) * Dd + h * DH + tx * 6 + j] = acc[i][j];
    }
}

// ---------------- layernorm: g_h = LN(g_tmp)*g + b ----------------
__global__ void __launch_bounds__(256) layernorm(const float* __restrict__ gam,
                                                 const float* __restrict__ bet) {
    __shared__ float sb[32];
    int row = blockIdx.x, tid = threadIdx.x;
    const float* x = g_tmp + (size_t)row * Dd;
    float v[3];
    #pragma unroll
    for (int i = 0; i < 3; i++) v[i] = x[tid + i * 256];
    float s = v[0] + v[1] + v[2];
    s = blockReduceSum256(s, sb);
    float mean = s / 768.0f;
    float d2 = 0.f;
    #pragma unroll
    for (int i = 0; i < 3; i++) { float d = v[i] - mean; d2 += d * d; }
    d2 = blockReduceSum256(d2, sb);
    float var = d2 / 768.0f;
    float inv = 1.0f / sqrtf(var + 1e-5f);
    #pragma unroll
    for (int i = 0; i < 3; i++) {
        int c = tid + i * 256;
        g_h[(size_t)row * Dd + c] = (v[i] - mean) * inv * gam[c] + bet[c];
    }
}

// ---------------- threefry2x32 (JAX-exact) ----------------
__device__ __forceinline__ uint32_t rotl32(uint32_t x, int d) {
    return (x << d) | (x >> (32 - d));
}
__device__ void threefry2x32(uint32_t k0, uint32_t k1, uint32_t x0, uint32_t x1,
                             uint32_t& o0, uint32_t& o1) {
    uint32_t k2 = k0 ^ k1 ^ 0x1BD11BDAu;
    x0 += k0; x1 += k1;
    x0 += x1; x1 = rotl32(x1, 13); x1 ^= x0;
    x0 += x1; x1 = rotl32(x1, 15); x1 ^= x0;
    x0 += x1; x1 = rotl32(x1, 26); x1 ^= x0;
    x0 += x1; x1 = rotl32(x1, 6);  x1 ^= x0;
    x0 += k1; x1 += k2 + 1u;
    x0 += x1; x1 = rotl32(x1, 17); x1 ^= x0;
    x0 += x1; x1 = rotl32(x1, 29); x1 ^= x0;
    x0 += x1; x1 = rotl32(x1, 16); x1 ^= x0;
    x0 += x1; x1 = rotl32(x1, 24); x1 ^= x0;
    x0 += k2; x1 += k0 + 2u;
    x0 += x1; x1 = rotl32(x1, 13); x1 ^= x0;
    x0 += x1; x1 = rotl32(x1, 15); x1 ^= x0;
    x0 += x1; x1 = rotl32(x1, 26); x1 ^= x0;
    x0 += x1; x1 = rotl32(x1, 6);  x1 ^= x0;
    x0 += k0; x1 += k1 + 3u;
    x0 += x1; x1 = rotl32(x1, 17); x1 ^= x0;
    x0 += x1; x1 = rotl32(x1, 29); x1 ^= x0;
    x0 += x1; x1 = rotl32(x1, 16); x1 ^= x0;
    x0 += x1; x1 = rotl32(x1, 24); x1 ^= x0;
    x0 += k1; x1 += k2 + 4u;
    x0 += x1; x1 = rotl32(x1, 13); x1 ^= x0;
    x0 += x1; x1 = rotl32(x1, 15); x1 ^= x0;
    x0 += x1; x1 = rotl32(x1, 26); x1 ^= x0;
    x0 += x1; x1 = rotl32(x1, 6);  x1 ^= x0;
    x0 += k2; x1 += k0 + 5u;
    o0 = x0; o1 = x1;
}

// ---------------- VQ top-10 + gumbel sample ----------------
__global__ void __launch_bounds__(256) vq_topk_sample() {
    int row = blockIdx.x, tid = threadIdx.x;
    const float* __restrict__ drow = g_dist + (size_t)row * Kc;
    float td[10]; int ti[10];
    #pragma unroll
    for (int j = 0; j < 10; j++) { td[j] = 3.4e38f; ti[j] = 0x7fffffff; }
    for (int c = tid; c < Kc; c += 256) {
        float v = drow[c];
        if (v < td[9] || (v == td[9] && c < ti[9])) {
            int pos = 9;
            #pragma unroll
            for (int j = 8; j >= 0; j--) {
                bool lt = (v < td[j]) || (v == td[j] && c < ti[j]);
                if (lt) pos = j;
            }
            #pragma unroll
            for (int j = 9; j > 0; j--)
                if (j > pos) { td[j] = td[j-1]; ti[j] = ti[j-1]; }
            td[pos] = v; ti[pos] = c;
        }
    }
    __shared__ float sd[2560];
    __shared__ int   si[2560];
    #pragma unroll
    for (int j = 0; j < 10; j++) { sd[tid * 10 + j] = td[j]; si[tid * 10 + j] = ti[j]; }
    for (int stride = 128; stride >= 1; stride >>= 1) {
        __syncthreads();
        if (tid < stride) {
            float od[10]; int oi[10];
            int a = 0, b2 = 0;
            #pragma unroll
            for (int j = 0; j < 10; j++) {
                float da = sd[tid * 10 + a], db = sd[(tid + stride) * 10 + b2];
                int   ia = si[tid * 10 + a], ib = si[(tid + stride) * 10 + b2];
                bool ta = (da < db) || (da == db && ia <= ib);
                if (ta) { od[j] = da; oi[j] = ia; a++; }
                else    { od[j] = db; oi[j] = ib; b2++; }
            }
            #pragma unroll
            for (int j = 0; j < 10; j++) { sd[tid * 10 + j] = od[j]; si[tid * 10 + j] = oi[j]; }
        }
    }
    __syncthreads();
    if (tid == 0) {
        float best = -3.4e38f;
        int bi = si[0];
        for (int j = 0; j < 10; j++) {
            uint32_t e = (uint32_t)(row * 10 + j);
            uint32_t o0, o1, bits;
#if JAX_PARTITIONABLE
            threefry2x32(0u, 42u, 0u, e, o0, o1);
            bits = o0 ^ o1;
#else
            if (e < 40960u) { threefry2x32(0u, 42u, e, e + 40960u, o0, o1); bits = o0; }
            else            { threefry2x32(0u, 42u, e - 40960u, e, o0, o1); bits = o1; }
#endif
            float u = __uint_as_float((bits >> 9) | 0x3f800000u) - 1.0f;
            u = u * 1.0f + 1e-10f;        // u*(maxval-minval)+minval
            u = fmaxf(1e-10f, u);
            float gmb = -logf(-logf(u));
            float sc = -sd[j] + gmb;      // neg_top/TEMP + gumbel, TEMP=1
            if (sc > best) { best = sc; bi = si[j]; }
        }
        g_enc[row] = bi;
    }
}

// ---------------- quantize: h = z_e + (codebook[enc] - z_e) ----------------
__global__ void __launch_bounds__(256) vq_quantize(const float* __restrict__ cb) {
    int row = blockIdx.x, tid = threadIdx.x;
    int e = g_enc[row];
    #pragma unroll
    for (int i = 0; i < 3; i++) {
        int c = tid + i * 256;
        float z = g_mem[(size_t)row * Dd + c];
        float q = cb[(size_t)e * Dd + c];
        g_h[(size_t)row * Dd + c] = z + (q - z);
    }
}

// ---------------- host ----------------
static void* sym(const void* devsym) {
    void* p = nullptr;
    cudaGetSymbolAddress(&p, devsym);
    return p;
}

extern "C" void kernel_launch(void* const* d_in, const int* in_sizes, int n_in,
                              void* d_out, int out_size) {
    const float* x       = (const float*)d_in[0];
    const float* cb      = (const float*)d_in[1];
    const float* sa_in_w = (const float*)d_in[2];
    const float* sa_in_b = (const float*)d_in[3];
    const float* sa_out_w= (const float*)d_in[4];
    const float* sa_out_b= (const float*)d_in[5];
    const float* ca_in_w = (const float*)d_in[6];
    const float* ca_in_b = (const float*)d_in[7];
    const float* ca_out_w= (const float*)d_in[8];
    const float* ca_out_b= (const float*)d_in[9];
    const float* ln1_g   = (const float*)d_in[10];
    const float* ln1_b   = (const float*)d_in[11];
    const float* ln2_g   = (const float*)d_in[12];
    const float* ln2_b   = (const float*)d_in[13];
    const float* ln3_g   = (const float*)d_in[14];
    const float* ln3_b   = (const float*)d_in[15];
    const float* ff_w1   = (const float*)d_in[16];
    const float* ff_b1   = (const float*)d_in[17];
    const float* ff_w2   = (const float*)d_in[18];
    const float* ff_b2   = (const float*)d_in[19];
    const float* out_w   = (const float*)d_in[20];
    const float* out_b   = (const float*)d_in[21];
    float* outp = (float*)d_out;

    float* p_mem   = (float*)sym(g_mem);
    float* p_h     = (float*)sym(g_h);
    float* p_tmp   = (float*)sym(g_tmp);
    float* p_attno = (float*)sym(g_attno);
    float* p_qkv   = (float*)sym(g_qkv);
    float* p_ff    = (float*)sym(g_ffbuf);
    float* p_dist  = (float*)sym(g_dist);
    float* p_xn    = (float*)sym(g_xnorm);
    float* p_cn    = (float*)sym(g_cnorm);

    auto GEMM = [](const float* A, int lda, const float* W, int ldw,
                   const float* bias, const float* resid, int ldr,
                   const float* rn, const float* cn,
                   float* C, int ldc, int M, int N, int K, int mode) {
        dim3 grid(N / 128, M / 128);
        sgemm_nt<<<grid, 256>>>(A, lda, W, ldw, bias, resid, ldr, rn, cn, C, ldc, K, mode);
    };

    // ---- VQ ----
    rowstat_x<<<NTOK, 256>>>(x);
    rowstat_cb<<<Kc, 256>>>(cb);
    GEMM(p_mem, Dd, cb, Dd, nullptr, nullptr, 0, p_xn, p_cn,
         p_dist, Kc, NTOK, Kc, Dd, 3);
    vq_topk_sample<<<NTOK, 256>>>();
    vq_quantize<<<NTOK, 256>>>(cb);

    // ---- decoder layers ----
    for (int l = 0; l < Ll; l++) {
        const float* siw = sa_in_w + (size_t)l * 3 * Dd * Dd;
        const float* sib = sa_in_b + (size_t)l * 3 * Dd;
        const float* sow = sa_out_w + (size_t)l * Dd * Dd;
        const float* sob = sa_out_b + (size_t)l * Dd;
        const float* ciw = ca_in_w + (size_t)l * 3 * Dd * Dd;
        const float* cib = ca_in_b + (size_t)l * 3 * Dd;
        const float* cow = ca_out_w + (size_t)l * Dd * Dd;
        const float* cob = ca_out_b + (size_t)l * Dd;

        // self-attention
        GEMM(p_h, Dd, siw, Dd, sib, nullptr, 0, nullptr, nullptr,
             p_qkv, 3 * Dd, NTOK, 3 * Dd, Dd, 0);
        attn_scores<<<dim3(8, 8, Bb * Hh), 256>>>(1);
        softmax512<<<Bb * Hh * Ss, 128>>>();
        attn_av<<<dim3(8, Bb * Hh), 256>>>();
        GEMM(p_attno, Dd, sow, Dd, sob, p_h, Dd, nullptr, nullptr,
             p_tmp, Dd, NTOK, Dd, Dd, 2);
        layernorm<<<NTOK, 256>>>(ln1_g + (size_t)l * Dd, ln1_b + (size_t)l * Dd);

        // cross-attention (q from h, k/v from mem)
        GEMM(p_h, Dd, ciw, Dd, cib, nullptr, 0, nullptr, nullptr,
             p_qkv, 3 * Dd, NTOK, Dd, Dd, 0);
        GEMM(p_mem, Dd, ciw + (size_t)Dd * Dd, Dd, cib + Dd, nullptr, 0, nullptr, nullptr,
             p_qkv + Dd, 3 * Dd, NTOK, 2 * Dd, Dd, 0);
        attn_scores<<<dim3(8, 8, Bb * Hh), 256>>>(0);
        softmax512<<<Bb * Hh * Ss, 128>>>();
        attn_av<<<dim3(8, Bb * Hh), 256>>>();
        GEMM(p_attno, Dd, cow, Dd, cob, p_h, Dd, nullptr, nullptr,
             p_tmp, Dd, NTOK, Dd, Dd, 2);
        layernorm<<<NTOK, 256>>>(ln2_g + (size_t)l * Dd, ln2_b + (size_t)l * Dd);

        // feed-forward
        GEMM(p_h, Dd, ff_w1 + (size_t)l * FFd * Dd, Dd, ff_b1 + (size_t)l * FFd,
             nullptr, 0, nullptr, nullptr, p_ff, FFd, NTOK, FFd, Dd, 1);
        GEMM(p_ff, FFd, ff_w2 + (size_t)l * Dd * FFd, FFd, ff_b2 + (size_t)l * Dd,
             p_h, Dd, nullptr, nullptr, p_tmp, Dd, NTOK, Dd, FFd, 2);
        layernorm<<<NTOK, 256>>>(ln3_g + (size_t)l * Dd, ln3_b + (size_t)l * Dd);
    }

    // ---- final projection ----
    GEMM(p_h, Dd, out_w, Dd, out_b, nullptr, 0, nullptr, nullptr,
         outp, Dd, NTOK, Dd, Dd, 0);
}

// round 6
// speedup vs baseline: 1.6477x; 1.6477x over previous
#include <cuda_runtime.h>
#include <cuda_bf16.h>
#include <cstdint>
#include <math.h>

#define Bb 16
#define Ss 512
#define Dd 768
#define Kc 8192
#define Hh 8
#define Ll 6
#define FFd 2048
#define NTOK 8192
#define DH 96
#define NEGB (-1e9f)
typedef __nv_bfloat16 bf16;

#define W_SAIN_N  (Ll * 3 * Dd * Dd)
#define W_SQ_N    (Ll * Dd * Dd)
#define W_FF1_N   (Ll * FFd * Dd)
#define W_FF2_N   (Ll * Dd * FFd)
#define W_OUT_N   (Dd * Dd)

// ---------------- scratch ----------------
__device__ __align__(256) float g_mem  [NTOK * Dd];
__device__ __align__(256) float g_h    [NTOK * Dd];
__device__ __align__(256) float g_tmp  [NTOK * Dd];
__device__ __align__(256) float g_qkv  [NTOK * 3 * Dd];
__device__ __align__(256) float g_scores[(size_t)Bb * Hh * Ss * Ss];
__device__ __align__(256) float g_dist [(size_t)NTOK * Kc];
__device__ float g_xnorm[NTOK];
__device__ float g_cnorm[Kc];
__device__ int   g_pad  [NTOK];
__device__ int   g_enc  [NTOK];

__device__ __align__(256) bf16 g_h_h[NTOK*Dd],  g_h_l[NTOK*Dd];
__device__ __align__(256) bf16 g_att_h[NTOK*Dd],g_att_l[NTOK*Dd];
__device__ __align__(256) bf16 g_mem_h[NTOK*Dd],g_mem_l[NTOK*Dd];
__device__ __align__(256) bf16 g_ff_h[NTOK*FFd],g_ff_l[NTOK*FFd];
__device__ __align__(256) bf16 g_wsain_h[W_SAIN_N], g_wsain_l[W_SAIN_N];
__device__ __align__(256) bf16 g_wsaout_h[W_SQ_N],  g_wsaout_l[W_SQ_N];
__device__ __align__(256) bf16 g_wcain_h[W_SAIN_N], g_wcain_l[W_SAIN_N];
__device__ __align__(256) bf16 g_wcaout_h[W_SQ_N],  g_wcaout_l[W_SQ_N];
__device__ __align__(256) bf16 g_wff1_h[W_FF1_N],   g_wff1_l[W_FF1_N];
__device__ __align__(256) bf16 g_wff2_h[W_FF2_N],   g_wff2_l[W_FF2_N];
__device__ __align__(256) bf16 g_wout_h[W_OUT_N],   g_wout_l[W_OUT_N];

// ---------------- helpers ----------------
__device__ __forceinline__ uint32_t smem_u32(const void* p) {
    uint32_t a;
    asm("{ .reg .u64 t; cvta.to.shared.u64 t, %1; cvt.u32.u64 %0, t; }" : "=r"(a) : "l"(p));
    return a;
}
#define CPA16(dst, src) \
    asm volatile("cp.async.cg.shared.global [%0], [%1], 16;" :: "r"(dst), "l"(src))

__device__ __forceinline__ void split2(float x, bf16& h, bf16& l) {
    h = __float2bfloat16(x);
    l = __float2bfloat16(x - __bfloat162float(h));
}
__device__ __forceinline__ void lm4(uint32_t addr, uint32_t* r) {
    asm volatile("ldmatrix.sync.aligned.m8n8.x4.shared.b16 {%0,%1,%2,%3}, [%4];"
        : "=r"(r[0]), "=r"(r[1]), "=r"(r[2]), "=r"(r[3]) : "r"(addr));
}
__device__ __forceinline__ void lm2(uint32_t addr, uint32_t* r) {
    asm volatile("ldmatrix.sync.aligned.m8n8.x2.shared.b16 {%0,%1}, [%2];"
        : "=r"(r[0]), "=r"(r[1]) : "r"(addr));
}
__device__ __forceinline__ void MMA(float* d, const uint32_t* a, const uint32_t* b) {
    asm volatile("mma.sync.aligned.m16n8k16.row.col.f32.bf16.bf16.f32 "
        "{%0,%1,%2,%3}, {%4,%5,%6,%7}, {%8,%9}, {%0,%1,%2,%3};"
        : "+f"(d[0]), "+f"(d[1]), "+f"(d[2]), "+f"(d[3])
        : "r"(a[0]), "r"(a[1]), "r"(a[2]), "r"(a[3]), "r"(b[0]), "r"(b[1]));
}

// ============ HMMA split-bf16 GEMM: C[M,N] = epi(A @ W^T) ============
// block 128x128, warp 64x32, K slab 32, double-buffered cp.async.
// mode 0: +bias->f32   1: relu(+bias)->split bf16   2: +bias+resid->f32
#define GM_STAGE 40960
#define GM_SMEM  (GM_STAGE * 2)

__global__ void __launch_bounds__(256, 1) gemm_mma(
    const bf16* __restrict__ Ahi, const bf16* __restrict__ Alo,
    const bf16* __restrict__ Whi, const bf16* __restrict__ Wlo,
    const float* __restrict__ bias, const float* __restrict__ resid, int ldr,
    float* __restrict__ C, bf16* __restrict__ Chi, bf16* __restrict__ Clo,
    int ldc, int K, int mode)
{
    extern __shared__ char smem[];
    const int tid = threadIdx.x, wid = tid >> 5, lane = tid & 31;
    const int bm = blockIdx.y * 128, bn = blockIdx.x * 128;
    const int wm = (wid & 1) * 64, wn = (wid >> 1) * 32;
    uint32_t sbase = smem_u32(smem);

    auto load_stage = [&](int s, int b) {
        uint32_t buf = sbase + b * GM_STAGE;
        #pragma unroll
        for (int i = 0; i < 8; i++) {
            int c = tid + i * 256;
            int tilei = c >> 9;          // 0 Ah, 1 Al, 2 Wh, 3 Wl
            int idx = c & 511;
            int row = idx >> 2, kch = (idx & 3) * 8;
            const bf16* src = (tilei == 0 ? Ahi : tilei == 1 ? Alo : tilei == 2 ? Whi : Wlo)
                + (size_t)((tilei < 2 ? bm : bn) + row) * K + s * 32 + kch;
            CPA16(buf + tilei * 10240 + row * 80 + kch * 2, src);
        }
        asm volatile("cp.async.commit_group;");
    };

    float acc[4][4][4];
    #pragma unroll
    for (int i = 0; i < 4; i++)
        #pragma unroll
        for (int j = 0; j < 4; j++)
            #pragma unroll
            for (int q = 0; q < 4; q++) acc[i][j][q] = 0.f;

    const int S = K >> 5;
    load_stage(0, 0);
    load_stage(1, 1);

    for (int s = 0; s < S; s++) {
        int b = s & 1;
        if (s >= S - 1) asm volatile("cp.async.wait_group 0;");
        else            asm volatile("cp.async.wait_group 1;");
        __syncthreads();
        uint32_t buf = sbase + b * GM_STAGE;
        #pragma unroll
        for (int ks = 0; ks < 2; ks++) {
            int k0 = ks * 16;
            uint32_t ah[4][4], al[4][4], bh[4][2], bl[4][2];
            int arow = wm + (lane & 15);
            int acol = (k0 + ((lane >> 4) & 1) * 8) * 2;
            #pragma unroll
            for (int mf = 0; mf < 4; mf++) {
                lm4(buf +         (arow + mf * 16) * 80 + acol, ah[mf]);
                lm4(buf + 10240 + (arow + mf * 16) * 80 + acol, al[mf]);
            }
            int l16 = lane & 15;
            int brow = wn + (l16 & 7);
            int bcol = (k0 + ((l16 >> 3) & 1) * 8) * 2;
            #pragma unroll
            for (int nf = 0; nf < 4; nf++) {
                lm2(buf + 20480 + (brow + nf * 8) * 80 + bcol, bh[nf]);
                lm2(buf + 30720 + (brow + nf * 8) * 80 + bcol, bl[nf]);
            }
            #pragma unroll
            for (int mf = 0; mf < 4; mf++)
                #pragma unroll
                for (int nf = 0; nf < 4; nf++) {
                    MMA(acc[mf][nf], ah[mf], bh[nf]);
                    MMA(acc[mf][nf], ah[mf], bl[nf]);
                    MMA(acc[mf][nf], al[mf], bh[nf]);
                }
        }
        __syncthreads();
        if (s + 2 < S) load_stage(s + 2, b);
    }

    // epilogue: direct global writes (float2 / ushort2 per fragment half)
    #pragma unroll
    for (int mf = 0; mf < 4; mf++)
        #pragma unroll
        for (int nf = 0; nf < 4; nf++)
            #pragma unroll
            for (int half = 0; half < 2; half++) {
                int row = bm + wm + mf * 16 + (lane >> 2) + half * 8;
                int col = bn + wn + nf * 8 + 2 * (lane & 3);
                float2 v = make_float2(acc[mf][nf][half * 2], acc[mf][nf][half * 2 + 1]);
                float2 bv = *(const float2*)(bias + col);
                v.x += bv.x; v.y += bv.y;
                size_t gr = (size_t)row;
                if (mode == 2) {
                    float2 r = *(const float2*)(resid + gr * ldr + col);
                    v.x += r.x; v.y += r.y;
                }
                if (mode == 1) {
                    v.x = fmaxf(v.x, 0.f); v.y = fmaxf(v.y, 0.f);
                    bf16 h0, l0, h1, l1;
                    split2(v.x, h0, l0); split2(v.y, h1, l1);
                    ushort2 hv, lv;
                    hv.x = __bfloat16_as_ushort(h0); hv.y = __bfloat16_as_ushort(h1);
                    lv.x = __bfloat16_as_ushort(l0); lv.y = __bfloat16_as_ushort(l1);
                    *(ushort2*)(Chi + gr * ldc + col) = hv;
                    *(ushort2*)(Clo + gr * ldc + col) = lv;
                } else {
                    *(float2*)(C + gr * ldc + col) = v;
                }
            }
}

// ---------------- reductions ----------------
__device__ __forceinline__ float bsum(float v, float* sb) {
    int tid = threadIdx.x;
    #pragma unroll
    for (int o = 16; o > 0; o >>= 1) v += __shfl_down_sync(0xffffffffu, v, o);
    if ((tid & 31) == 0) sb[tid >> 5] = v;
    __syncthreads();
    float s = 0.f;
    if (tid < 32) {
        s = (tid < (int)(blockDim.x >> 5)) ? sb[tid] : 0.f;
        #pragma unroll
        for (int o = 16; o > 0; o >>= 1) s += __shfl_down_sync(0xffffffffu, s, o);
        if (tid == 0) sb[0] = s;
    }
    __syncthreads();
    float r = sb[0]; __syncthreads(); return r;
}
__device__ __forceinline__ float bmax(float v, float* sb) {
    int tid = threadIdx.x;
    #pragma unroll
    for (int o = 16; o > 0; o >>= 1) v = fmaxf(v, __shfl_down_sync(0xffffffffu, v, o));
    if ((tid & 31) == 0) sb[tid >> 5] = v;
    __syncthreads();
    float s = -3.4e38f;
    if (tid < 32) {
        s = (tid < (int)(blockDim.x >> 5)) ? sb[tid] : -3.4e38f;
        #pragma unroll
        for (int o = 16; o > 0; o >>= 1) s = fmaxf(s, __shfl_down_sync(0xffffffffu, s, o));
        if (tid == 0) sb[0] = s;
    }
    __syncthreads();
    float r = sb[0]; __syncthreads(); return r;
}

// ---------------- small kernels ----------------
__global__ void __launch_bounds__(256) cvt_split(const float* __restrict__ x,
                                                 bf16* __restrict__ hi, bf16* __restrict__ lo, int n4) {
    int i = blockIdx.x * 256 + threadIdx.x;
    if (i >= n4) return;
    float4 v = ((const float4*)x)[i];
    bf16 h0,l0,h1,l1,h2,l2,h3,l3;
    split2(v.x,h0,l0); split2(v.y,h1,l1); split2(v.z,h2,l2); split2(v.w,h3,l3);
    ushort4 hv, lv;
    hv.x=__bfloat16_as_ushort(h0); hv.y=__bfloat16_as_ushort(h1);
    hv.z=__bfloat16_as_ushort(h2); hv.w=__bfloat16_as_ushort(h3);
    lv.x=__bfloat16_as_ushort(l0); lv.y=__bfloat16_as_ushort(l1);
    lv.z=__bfloat16_as_ushort(l2); lv.w=__bfloat16_as_ushort(l3);
    ((ushort4*)hi)[i] = hv; ((ushort4*)lo)[i] = lv;
}

__global__ void __launch_bounds__(256) rowstat_x(const float* __restrict__ x) {
    __shared__ float sb[32];
    int row = blockIdx.x, tid = threadIdx.x;
    float v[3];
    #pragma unroll
    for (int i = 0; i < 3; i++) v[i] = x[(size_t)row * Dd + tid + i * 256];
    float ss = v[0]*v[0] + v[1]*v[1] + v[2]*v[2];
    ss = bsum(ss, sb);
    int pad = (sqrtf(ss) <= 1e-6f) ? 1 : 0;
    if (tid == 0) { g_pad[row] = pad; g_xnorm[row] = pad ? 0.f : ss; }
    #pragma unroll
    for (int i = 0; i < 3; i++) {
        int c = tid + i * 256;
        float o = pad ? 0.f : v[i];
        g_mem[(size_t)row * Dd + c] = o;
        bf16 hh, ll; split2(o, hh, ll);
        g_mem_h[(size_t)row * Dd + c] = hh;
        g_mem_l[(size_t)row * Dd + c] = ll;
    }
}
__global__ void __launch_bounds__(256) rowstat_cb(const float* __restrict__ cb) {
    __shared__ float sb[32];
    int row = blockIdx.x, tid = threadIdx.x;
    float ss = 0.f;
    #pragma unroll
    for (int i = 0; i < 3; i++) { float v = cb[(size_t)row * Dd + tid + i * 256]; ss += v * v; }
    ss = bsum(ss, sb);
    if (tid == 0) g_cnorm[row] = ss;
}

// ---------------- fp32 NT SGEMM (VQ distances) ----------------
__global__ void __launch_bounds__(256) sgemm_nt(
    const float* __restrict__ A, const float* __restrict__ W,
    const float* __restrict__ rnorm, const float* __restrict__ cnorm,
    float* __restrict__ C, int ldc, int K)
{
    __shared__ float As[16][132];
    __shared__ float Ws[16][132];
    const int bm = blockIdx.y * 128, bn = blockIdx.x * 128;
    const int tid = threadIdx.x, tx = tid & 15, ty = tid >> 4;
    float acc[8][8];
    #pragma unroll
    for (int i = 0; i < 8; i++)
        #pragma unroll
        for (int j = 0; j < 8; j++) acc[i][j] = 0.f;
    for (int k0 = 0; k0 < K; k0 += 16) {
        #pragma unroll
        for (int u = 0; u < 2; u++) {
            int f = tid + u * 256;
            int row = f >> 2, c4 = (f & 3) << 2;
            float4 a = *(const float4*)(A + (size_t)(bm + row) * K + k0 + c4);
            As[c4+0][row]=a.x; As[c4+1][row]=a.y; As[c4+2][row]=a.z; As[c4+3][row]=a.w;
            float4 w = *(const float4*)(W + (size_t)(bn + row) * K + k0 + c4);
            Ws[c4+0][row]=w.x; Ws[c4+1][row]=w.y; Ws[c4+2][row]=w.z; Ws[c4+3][row]=w.w;
        }
        __syncthreads();
        #pragma unroll
        for (int kk = 0; kk < 16; kk++) {
            float a[8], b[8];
            *(float4*)(a)   = *(const float4*)&As[kk][ty*8];
            *(float4*)(a+4) = *(const float4*)&As[kk][ty*8+4];
            *(float4*)(b)   = *(const float4*)&Ws[kk][tx*8];
            *(float4*)(b+4) = *(const float4*)&Ws[kk][tx*8+4];
            #pragma unroll
            for (int i = 0; i < 8; i++)
                #pragma unroll
                for (int j = 0; j < 8; j++) acc[i][j] = fmaf(a[i], b[j], acc[i][j]);
        }
        __syncthreads();
    }
    #pragma unroll
    for (int i = 0; i < 8; i++) {
        int row = bm + ty * 8 + i;
        float xn = rnorm[row];
        #pragma unroll
        for (int jj = 0; jj < 8; jj += 4) {
            int col = bn + tx * 8 + jj;
            float4 v;
            v.x = (xn + cnorm[col+0]) - 2.f*acc[i][jj];
            v.y = (xn + cnorm[col+1]) - 2.f*acc[i][jj+1];
            v.z = (xn + cnorm[col+2]) - 2.f*acc[i][jj+2];
            v.w = (xn + cnorm[col+3]) - 2.f*acc[i][jj+3];
            *(float4*)(C + (size_t)row * ldc + col) = v;
        }
    }
}

// ---------------- attention (fp32) ----------------
__global__ void __launch_bounds__(256) attn_scores(int causal) {
    __shared__ float Qs[32][68];
    __shared__ float Ks[32][68];
    int kt = blockIdx.x, qt = blockIdx.y, bh = blockIdx.z;
    int b = bh >> 3, h = bh & 7;
    const float* __restrict__ Qb = g_qkv + (size_t)b * Ss * 3 * Dd + h * DH;
    const float* __restrict__ Kb = Qb + Dd;
    int tid = threadIdx.x, tx = tid & 15, ty = tid >> 4;
    float acc[4][4];
    #pragma unroll
    for (int i = 0; i < 4; i++)
        #pragma unroll
        for (int j = 0; j < 4; j++) acc[i][j] = 0.f;
    for (int k0 = 0; k0 < DH; k0 += 32) {
        #pragma unroll
        for (int u = 0; u < 2; u++) {
            int f = tid + u * 256;
            int row = f >> 3, c4 = (f & 7) << 2;
            float4 q = *(const float4*)(Qb + (size_t)(qt*64+row)*(3*Dd) + k0 + c4);
            Qs[c4+0][row]=q.x; Qs[c4+1][row]=q.y; Qs[c4+2][row]=q.z; Qs[c4+3][row]=q.w;
            float4 kv = *(const float4*)(Kb + (size_t)(kt*64+row)*(3*Dd) + k0 + c4);
            Ks[c4+0][row]=kv.x; Ks[c4+1][row]=kv.y; Ks[c4+2][row]=kv.z; Ks[c4+3][row]=kv.w;
        }
        __syncthreads();
        #pragma unroll
        for (int kk = 0; kk < 32; kk++) {
            float a[4], bfr[4];
            *(float4*)a   = *(const float4*)&Qs[kk][ty*4];
            *(float4*)bfr = *(const float4*)&Ks[kk][tx*4];
            #pragma unroll
            for (int i = 0; i < 4; i++)
                #pragma unroll
                for (int j = 0; j < 4; j++) acc[i][j] = fmaf(a[i], bfr[j], acc[i][j]);
        }
        __syncthreads();
    }
    const float scale = 9.797958971132712f;
    #pragma unroll
    for (int i = 0; i < 4; i++) {
        int q = qt * 64 + ty * 4 + i;
        float4 v; float* pv = &v.x;
        #pragma unroll
        for (int j = 0; j < 4; j++) {
            int k = kt * 64 + tx * 4 + j;
            float s = acc[i][j] / scale;
            if (causal && q > k) s += NEGB;
            if (g_pad[b * Ss + k]) s += NEGB;
            pv[j] = s;
        }
        *(float4*)(g_scores + ((size_t)bh * Ss + q) * Ss + kt * 64 + tx * 4) = v;
    }
}

__global__ void __launch_bounds__(128) softmax512() {
    __shared__ float sb[32];
    float* p = g_scores + (size_t)blockIdx.x * Ss;
    int tid = threadIdx.x;
    float4 v = *(const float4*)(p + tid * 4);
    float m = fmaxf(fmaxf(v.x, v.y), fmaxf(v.z, v.w));
    m = bmax(m, sb);
    float4 e;
    e.x = expf(v.x-m); e.y = expf(v.y-m); e.z = expf(v.z-m); e.w = expf(v.w-m);
    float s = e.x + e.y + e.z + e.w;
    s = bsum(s, sb);
    float inv = 1.0f / s;
    e.x *= inv; e.y *= inv; e.z *= inv; e.w *= inv;
    *(float4*)(p + tid * 4) = e;
}

__global__ void __launch_bounds__(256) attn_av() {
    __shared__ float Ps[16][68];
    __shared__ float Vs[16][96];
    int qt = blockIdx.x, bh = blockIdx.y;
    int b = bh >> 3, h = bh & 7;
    const float* __restrict__ P = g_scores + (size_t)bh * Ss * Ss + (size_t)qt * 64 * Ss;
    const float* __restrict__ Vb = g_qkv + (size_t)b * Ss * 3 * Dd + 2 * Dd + h * DH;
    int tid = threadIdx.x, tx = tid & 15, ty = tid >> 4;
    float acc[4][6];
    #pragma unroll
    for (int i = 0; i < 4; i++)
        #pragma unroll
        for (int j = 0; j < 6; j++) acc[i][j] = 0.f;
    for (int k0 = 0; k0 < Ss; k0 += 16) {
        {
            int row = tid >> 2, c4 = (tid & 3) << 2;
            float4 pv = *(const float4*)(P + (size_t)row * Ss + k0 + c4);
            Ps[c4+0][row]=pv.x; Ps[c4+1][row]=pv.y; Ps[c4+2][row]=pv.z; Ps[c4+3][row]=pv.w;
        }
        #pragma unroll
        for (int u = 0; u < 6; u++) {
            int f = tid + u * 256;
            int r = f / 96, c = f - r * 96;
            Vs[r][c] = Vb[(size_t)(k0 + r) * (3 * Dd) + c];
        }
        __syncthreads();
        #pragma unroll
        for (int kk = 0; kk < 16; kk++) {
            float a[4];
            *(float4*)a = *(const float4*)&Ps[kk][ty*4];
            float bf[6];
            #pragma unroll
            for (int j = 0; j < 6; j++) bf[j] = Vs[kk][tx*6+j];
            #pragma unroll
            for (int i = 0; i < 4; i++)
                #pragma unroll
                for (int j = 0; j < 6; j++) acc[i][j] = fmaf(a[i], bf[j], acc[i][j]);
        }
        __syncthreads();
    }
    #pragma unroll
    for (int i = 0; i < 4; i++) {
        int q = qt * 64 + ty * 4 + i;
        size_t base = (size_t)(b * Ss + q) * Dd + h * DH + tx * 6;
        #pragma unroll
        for (int j = 0; j < 6; j += 2) {
            bf16 h0,l0,h1,l1;
            split2(acc[i][j], h0, l0); split2(acc[i][j+1], h1, l1);
            __nv_bfloat162 hp, lp;
            hp.x = h0; hp.y = h1; lp.x = l0; lp.y = l1;
            *(__nv_bfloat162*)(g_att_h + base + j) = hp;
            *(__nv_bfloat162*)(g_att_l + base + j) = lp;
        }
    }
}

// ---------------- layernorm (+split) ----------------
__global__ void __launch_bounds__(256) layernorm(const float* __restrict__ gam,
                                                 const float* __restrict__ bet) {
    __shared__ float sb[32];
    int row = blockIdx.x, tid = threadIdx.x;
    const float* x = g_tmp + (size_t)row * Dd;
    float v[3];
    #pragma unroll
    for (int i = 0; i < 3; i++) v[i] = x[tid + i * 256];
    float s = bsum(v[0] + v[1] + v[2], sb);
    float mean = s / 768.0f;
    float d2 = 0.f;
    #pragma unroll
    for (int i = 0; i < 3; i++) { float d = v[i] - mean; d2 += d * d; }
    d2 = bsum(d2, sb);
    float inv = 1.0f / sqrtf(d2 / 768.0f + 1e-5f);
    #pragma unroll
    for (int i = 0; i < 3; i++) {
        int c = tid + i * 256;
        float o = (v[i] - mean) * inv * gam[c] + bet[c];
        g_h[(size_t)row * Dd + c] = o;
        bf16 hh, ll; split2(o, hh, ll);
        g_h_h[(size_t)row * Dd + c] = hh;
        g_h_l[(size_t)row * Dd + c] = ll;
    }
}

// ---------------- threefry (JAX-exact) ----------------
__device__ __forceinline__ uint32_t rotl32(uint32_t x, int d) { return (x << d) | (x >> (32 - d)); }
__device__ void threefry2x32(uint32_t k0, uint32_t k1, uint32_t x0, uint32_t x1,
                             uint32_t& o0, uint32_t& o1) {
    uint32_t k2 = k0 ^ k1 ^ 0x1BD11BDAu;
    x0 += k0; x1 += k1;
    x0+=x1; x1=rotl32(x1,13); x1^=x0;  x0+=x1; x1=rotl32(x1,15); x1^=x0;
    x0+=x1; x1=rotl32(x1,26); x1^=x0;  x0+=x1; x1=rotl32(x1,6);  x1^=x0;
    x0 += k1; x1 += k2 + 1u;
    x0+=x1; x1=rotl32(x1,17); x1^=x0;  x0+=x1; x1=rotl32(x1,29); x1^=x0;
    x0+=x1; x1=rotl32(x1,16); x1^=x0;  x0+=x1; x1=rotl32(x1,24); x1^=x0;
    x0 += k2; x1 += k0 + 2u;
    x0+=x1; x1=rotl32(x1,13); x1^=x0;  x0+=x1; x1=rotl32(x1,15); x1^=x0;
    x0+=x1; x1=rotl32(x1,26); x1^=x0;  x0+=x1; x1=rotl32(x1,6);  x1^=x0;
    x0 += k0; x1 += k1 + 3u;
    x0+=x1; x1=rotl32(x1,17); x1^=x0;  x0+=x1; x1=rotl32(x1,29); x1^=x0;
    x0+=x1; x1=rotl32(x1,16); x1^=x0;  x0+=x1; x1=rotl32(x1,24); x1^=x0;
    x0 += k1; x1 += k2 + 4u;
    x0+=x1; x1=rotl32(x1,13); x1^=x0;  x0+=x1; x1=rotl32(x1,15); x1^=x0;
    x0+=x1; x1=rotl32(x1,26); x1^=x0;  x0+=x1; x1=rotl32(x1,6);  x1^=x0;
    x0 += k2; x1 += k0 + 5u;
    o0 = x0; o1 = x1;
}

// ---------------- VQ top-10 + gumbel ----------------
__global__ void __launch_bounds__(256) vq_topk_sample() {
    int row = blockIdx.x, tid = threadIdx.x;
    const float* __restrict__ drow = g_dist + (size_t)row * Kc;
    float td[10]; int ti[10];
    #pragma unroll
    for (int j = 0; j < 10; j++) { td[j] = 3.4e38f; ti[j] = 0x7fffffff; }
    for (int c = tid; c < Kc; c += 256) {
        float v = drow[c];
        if (v < td[9] || (v == td[9] && c < ti[9])) {
            int pos = 9;
            #pragma unroll
            for (int j = 8; j >= 0; j--) {
                bool lt = (v < td[j]) || (v == td[j] && c < ti[j]);
                if (lt) pos = j;
            }
            #pragma unroll
            for (int j = 9; j > 0; j--)
                if (j > pos) { td[j] = td[j-1]; ti[j] = ti[j-1]; }
            td[pos] = v; ti[pos] = c;
        }
    }
    __shared__ float sd[2560];
    __shared__ int   si[2560];
    #pragma unroll
    for (int j = 0; j < 10; j++) { sd[tid*10+j] = td[j]; si[tid*10+j] = ti[j]; }
    for (int stride = 128; stride >= 1; stride >>= 1) {
        __syncthreads();
        if (tid < stride) {
            float od[10]; int oi[10];
            int a = 0, b2 = 0;
            #pragma unroll
            for (int j = 0; j < 10; j++) {
                float da = sd[tid*10+a], db = sd[(tid+stride)*10+b2];
                int   ia = si[tid*10+a], ib = si[(tid+stride)*10+b2];
                bool ta = (da < db) || (da == db && ia <= ib);
                if (ta) { od[j]=da; oi[j]=ia; a++; } else { od[j]=db; oi[j]=ib; b2++; }
            }
            #pragma unroll
            for (int j = 0; j < 10; j++) { sd[tid*10+j]=od[j]; si[tid*10+j]=oi[j]; }
        }
    }
    __syncthreads();
    if (tid == 0) {
        float best = -3.4e38f;
        int bi = si[0];
        for (int j = 0; j < 10; j++) {
            uint32_t e = (uint32_t)(row * 10 + j);
            uint32_t o0, o1;
            threefry2x32(0u, 42u, 0u, e, o0, o1);
            uint32_t bits = o0 ^ o1;
            float u = __uint_as_float((bits >> 9) | 0x3f800000u) - 1.0f;
            u = fmaxf(1e-10f, u + 1e-10f);
            float gmb = -logf(-logf(u));
            float sc = -sd[j] + gmb;
            if (sc > best) { best = sc; bi = si[j]; }
        }
        g_enc[row] = bi;
    }
}

__global__ void __launch_bounds__(256) vq_quantize(const float* __restrict__ cb) {
    int row = blockIdx.x, tid = threadIdx.x;
    int e = g_enc[row];
    #pragma unroll
    for (int i = 0; i < 3; i++) {
        int c = tid + i * 256;
        float z = g_mem[(size_t)row * Dd + c];
        float q = cb[(size_t)e * Dd + c];
        float o = z + (q - z);
        g_h[(size_t)row * Dd + c] = o;
        bf16 hh, ll; split2(o, hh, ll);
        g_h_h[(size_t)row * Dd + c] = hh;
        g_h_l[(size_t)row * Dd + c] = ll;
    }
}

// ---------------- host ----------------
static void* sym(const void* s) { void* p = nullptr; cudaGetSymbolAddress(&p, s); return p; }

extern "C" void kernel_launch(void* const* d_in, const int* in_sizes, int n_in,
                              void* d_out, int out_size) {
    const float* x     = (const float*)d_in[0];
    const float* cb    = (const float*)d_in[1];
    const float* sib   = (const float*)d_in[3];
    const float* sob   = (const float*)d_in[5];
    const float* cib   = (const float*)d_in[7];
    const float* cob   = (const float*)d_in[9];
    const float* ln1g  = (const float*)d_in[10];
    const float* ln1b  = (const float*)d_in[11];
    const float* ln2g  = (const float*)d_in[12];
    const float* ln2b  = (const float*)d_in[13];
    const float* ln3g  = (const float*)d_in[14];
    const float* ln3b  = (const float*)d_in[15];
    const float* fb1   = (const float*)d_in[17];
    const float* fb2   = (const float*)d_in[19];
    const float* outb  = (const float*)d_in[21];
    float* outp = (float*)d_out;

    cudaFuncSetAttribute(gemm_mma, cudaFuncAttributeMaxDynamicSharedMemorySize, GM_SMEM);

    float* p_mem  = (float*)sym(g_mem);
    float* p_h    = (float*)sym(g_h);
    float* p_tmp  = (float*)sym(g_tmp);
    float* p_qkv  = (float*)sym(g_qkv);
    float* p_dist = (float*)sym(g_dist);
    float* p_xn   = (float*)sym(g_xnorm);
    float* p_cn   = (float*)sym(g_cnorm);
    bf16 *hh = (bf16*)sym(g_h_h),   *hl = (bf16*)sym(g_h_l);
    bf16 *ah = (bf16*)sym(g_att_h), *al = (bf16*)sym(g_att_l);
    bf16 *mh = (bf16*)sym(g_mem_h), *ml = (bf16*)sym(g_mem_l);
    bf16 *fh = (bf16*)sym(g_ff_h),  *fl = (bf16*)sym(g_ff_l);
    bf16 *wsa_h = (bf16*)sym(g_wsain_h),  *wsa_l = (bf16*)sym(g_wsain_l);
    bf16 *wso_h = (bf16*)sym(g_wsaout_h), *wso_l = (bf16*)sym(g_wsaout_l);
    bf16 *wca_h = (bf16*)sym(g_wcain_h),  *wca_l = (bf16*)sym(g_wcain_l);
    bf16 *wco_h = (bf16*)sym(g_wcaout_h), *wco_l = (bf16*)sym(g_wcaout_l);
    bf16 *wf1_h = (bf16*)sym(g_wff1_h),   *wf1_l = (bf16*)sym(g_wff1_l);
    bf16 *wf2_h = (bf16*)sym(g_wff2_h),   *wf2_l = (bf16*)sym(g_wff2_l);
    bf16 *wo_h  = (bf16*)sym(g_wout_h),   *wo_l  = (bf16*)sym(g_wout_l);

    auto CVT = [](const float* s, bf16* h, bf16* l, size_t n) {
        int n4 = (int)(n / 4);
        cvt_split<<<(n4 + 255) / 256, 256>>>(s, h, l, n4);
    };
    auto TG = [&](const bf16* Ah, const bf16* Al, const bf16* Wh, const bf16* Wl,
                  const float* bias, const float* resid, float* C, bf16* Ch, bf16* Cl,
                  int ldc, int N, int K, int mode) {
        dim3 grid(N / 128, NTOK / 128);
        gemm_mma<<<grid, 256, GM_SMEM>>>(Ah, Al, Wh, Wl, bias, resid, Dd, C, Ch, Cl, ldc, K, mode);
    };

    CVT((const float*)d_in[2],  wsa_h, wsa_l, (size_t)W_SAIN_N);
    CVT((const float*)d_in[4],  wso_h, wso_l, (size_t)W_SQ_N);
    CVT((const float*)d_in[6],  wca_h, wca_l, (size_t)W_SAIN_N);
    CVT((const float*)d_in[8],  wco_h, wco_l, (size_t)W_SQ_N);
    CVT((const float*)d_in[16], wf1_h, wf1_l, (size_t)W_FF1_N);
    CVT((const float*)d_in[18], wf2_h, wf2_l, (size_t)W_FF2_N);
    CVT((const float*)d_in[20], wo_h,  wo_l,  (size_t)W_OUT_N);

    // VQ (fp32 exact)
    rowstat_x<<<NTOK, 256>>>(x);
    rowstat_cb<<<Kc, 256>>>(cb);
    {
        dim3 grid(Kc / 128, NTOK / 128);
        sgemm_nt<<<grid, 256>>>(p_mem, cb, p_xn, p_cn, p_dist, Kc, Dd);
    }
    vq_topk_sample<<<NTOK, 256>>>();
    vq_quantize<<<NTOK, 256>>>(cb);

    for (int l = 0; l < Ll; l++) {
        size_t win = (size_t)l * 3 * Dd * Dd, wsq = (size_t)l * Dd * Dd;
        // self-attention
        TG(hh, hl, wsa_h + win, wsa_l + win, sib + (size_t)l*3*Dd, nullptr,
           p_qkv, nullptr, nullptr, 3*Dd, 3*Dd, Dd, 0);
        attn_scores<<<dim3(8, 8, Bb*Hh), 256>>>(1);
        softmax512<<<Bb*Hh*Ss, 128>>>();
        attn_av<<<dim3(8, Bb*Hh), 256>>>();
        TG(ah, al, wso_h + wsq, wso_l + wsq, sob + (size_t)l*Dd, p_h,
           p_tmp, nullptr, nullptr, Dd, Dd, Dd, 2);
        layernorm<<<NTOK, 256>>>(ln1g + (size_t)l*Dd, ln1b + (size_t)l*Dd);

        // cross-attention
        TG(hh, hl, wca_h + win, wca_l + win, cib + (size_t)l*3*Dd, nullptr,
           p_qkv, nullptr, nullptr, 3*Dd, Dd, Dd, 0);
        TG(mh, ml, wca_h + win + (size_t)Dd*Dd, wca_l + win + (size_t)Dd*Dd,
           cib + (size_t)l*3*Dd + Dd, nullptr,
           p_qkv + Dd, nullptr, nullptr, 3*Dd, 2*Dd, Dd, 0);
        attn_scores<<<dim3(8, 8, Bb*Hh), 256>>>(0);
        softmax512<<<Bb*Hh*Ss, 128>>>();
        attn_av<<<dim3(8, Bb*Hh), 256>>>();
        TG(ah, al, wco_h + wsq, wco_l + wsq, cob + (size_t)l*Dd, p_h,
           p_tmp, nullptr, nullptr, Dd, Dd, Dd, 2);
        layernorm<<<NTOK, 256>>>(ln2g + (size_t)l*Dd, ln2b + (size_t)l*Dd);

        // feed-forward
        TG(hh, hl, wf1_h + (size_t)l*FFd*Dd, wf1_l + (size_t)l*FFd*Dd,
           fb1 + (size_t)l*FFd, nullptr, nullptr, fh, fl, FFd, FFd, Dd, 1);
        TG(fh, fl, wf2_h + (size_t)l*Dd*FFd, wf2_l + (size_t)l*Dd*FFd,
           fb2 + (size_t)l*Dd, p_h, p_tmp, nullptr, nullptr, Dd, Dd, FFd, 2);
        layernorm<<<NTOK, 256>>>(ln3g + (size_t)l*Dd, ln3b + (size_t)l*Dd);
    }

    TG(hh, hl, wo_h, wo_l, outb, nullptr, outp, nullptr, nullptr, Dd, Dd, Dd, 0);
}

// round 9
// speedup vs baseline: 2.0149x; 1.2228x over previous
#include <cuda_runtime.h>
#include <cuda_bf16.h>
#include <cstdint>
#include <math.h>

#define Bb 16
#define Ss 512
#define Dd 768
#define Kc 8192
#define Hh 8
#define Ll 6
#define FFd 2048
#define NTOK 8192
#define DH 96
#define NEGB (-1e9f)
typedef __nv_bfloat16 bf16;

#define W_SAIN_N  (Ll * 3 * Dd * Dd)
#define W_SQ_N    (Ll * Dd * Dd)
#define W_FF1_N   (Ll * FFd * Dd)
#define W_FF2_N   (Ll * Dd * FFd)
#define W_OUT_N   (Dd * Dd)

// ---------------- scratch ----------------
__device__ __align__(256) float g_mem  [NTOK * Dd];
__device__ __align__(256) float g_h    [NTOK * Dd];
__device__ __align__(256) float g_tmp  [NTOK * Dd];
__device__ __align__(256) float g_dist [(size_t)NTOK * Kc];
__device__ float g_xnorm[NTOK];
__device__ float g_cnorm[Kc];
__device__ float g_padf [NTOK];
__device__ int   g_pad  [NTOK];
__device__ int   g_enc  [NTOK];

__device__ __align__(256) bf16 g_qkvh[NTOK*3*Dd], g_qkvl[NTOK*3*Dd];
__device__ __align__(256) bf16 g_h_h[NTOK*Dd],  g_h_l[NTOK*Dd];
__device__ __align__(256) bf16 g_att_h[NTOK*Dd],g_att_l[NTOK*Dd];
__device__ __align__(256) bf16 g_mem_h[NTOK*Dd],g_mem_l[NTOK*Dd];
__device__ __align__(256) bf16 g_ff_h[NTOK*FFd],g_ff_l[NTOK*FFd];
__device__ __align__(256) bf16 g_wsain_h[W_SAIN_N], g_wsain_l[W_SAIN_N];
__device__ __align__(256) bf16 g_wsaout_h[W_SQ_N],  g_wsaout_l[W_SQ_N];
__device__ __align__(256) bf16 g_wcain_h[W_SAIN_N], g_wcain_l[W_SAIN_N];
__device__ __align__(256) bf16 g_wcaout_h[W_SQ_N],  g_wcaout_l[W_SQ_N];
__device__ __align__(256) bf16 g_wff1_h[W_FF1_N],   g_wff1_l[W_FF1_N];
__device__ __align__(256) bf16 g_wff2_h[W_FF2_N],   g_wff2_l[W_FF2_N];
__device__ __align__(256) bf16 g_wout_h[W_OUT_N],   g_wout_l[W_OUT_N];

// ---------------- helpers ----------------
__device__ __forceinline__ uint32_t smem_u32(const void* p) {
    uint32_t a;
    asm("{ .reg .u64 t; cvta.to.shared.u64 t, %1; cvt.u32.u64 %0, t; }" : "=r"(a) : "l"(p));
    return a;
}
#define CPA16(dst, src) \
    asm volatile("cp.async.cg.shared.global [%0], [%1], 16;" :: "r"(dst), "l"(src))

__device__ __forceinline__ void split2(float x, bf16& h, bf16& l) {
    h = __float2bfloat16(x);
    l = __float2bfloat16(x - __bfloat162float(h));
}
__device__ __forceinline__ uint32_t packsplit(float x, float y, uint32_t& lo) {
    bf16 hx, lx, hy, ly;
    split2(x, hx, lx); split2(y, hy, ly);
    lo = ((uint32_t)__bfloat16_as_ushort(ly) << 16) | __bfloat16_as_ushort(lx);
    return ((uint32_t)__bfloat16_as_ushort(hy) << 16) | __bfloat16_as_ushort(hx);
}
__device__ __forceinline__ void lm4(uint32_t addr, uint32_t* r) {
    asm volatile("ldmatrix.sync.aligned.m8n8.x4.shared.b16 {%0,%1,%2,%3}, [%4];"
        : "=r"(r[0]), "=r"(r[1]), "=r"(r[2]), "=r"(r[3]) : "r"(addr));
}
__device__ __forceinline__ void lm2(uint32_t addr, uint32_t* r) {
    asm volatile("ldmatrix.sync.aligned.m8n8.x2.shared.b16 {%0,%1}, [%2];"
        : "=r"(r[0]), "=r"(r[1]) : "r"(addr));
}
__device__ __forceinline__ void lm2t(uint32_t addr, uint32_t* r) {
    asm volatile("ldmatrix.sync.aligned.m8n8.x2.trans.shared.b16 {%0,%1}, [%2];"
        : "=r"(r[0]), "=r"(r[1]) : "r"(addr));
}
__device__ __forceinline__ void MMA(float* d, const uint32_t* a, const uint32_t* b) {
    asm volatile("mma.sync.aligned.m16n8k16.row.col.f32.bf16.bf16.f32 "
        "{%0,%1,%2,%3}, {%4,%5,%6,%7}, {%8,%9}, {%0,%1,%2,%3};"
        : "+f"(d[0]), "+f"(d[1]), "+f"(d[2]), "+f"(d[3])
        : "r"(a[0]), "r"(a[1]), "r"(a[2]), "r"(a[3]), "r"(b[0]), "r"(b[1]));
}

// ============ HMMA split-bf16 GEMM ============
// mode 0: +bias->f32  1: relu(+bias)->split  2: +bias+resid->f32  3: +bias->split
#define GM_STAGE 40960
#define GM_SMEM  (GM_STAGE * 2)

__global__ void __launch_bounds__(256, 1) gemm_mma(
    const bf16* __restrict__ Ahi, const bf16* __restrict__ Alo,
    const bf16* __restrict__ Whi, const bf16* __restrict__ Wlo,
    const float* __restrict__ bias, const float* __restrict__ resid, int ldr,
    float* __restrict__ C, bf16* __restrict__ Chi, bf16* __restrict__ Clo,
    int ldc, int K, int mode)
{
    extern __shared__ char smem[];
    const int tid = threadIdx.x, wid = tid >> 5, lane = tid & 31;
    const int bm = blockIdx.y * 128, bn = blockIdx.x * 128;
    const int wm = (wid & 1) * 64, wn = (wid >> 1) * 32;
    uint32_t sbase = smem_u32(smem);

    auto load_stage = [&](int s, int b) {
        uint32_t buf = sbase + b * GM_STAGE;
        #pragma unroll
        for (int i = 0; i < 8; i++) {
            int c = tid + i * 256;
            int tilei = c >> 9;
            int idx = c & 511;
            int row = idx >> 2, kch = (idx & 3) * 8;
            const bf16* src = (tilei == 0 ? Ahi : tilei == 1 ? Alo : tilei == 2 ? Whi : Wlo)
                + (size_t)((tilei < 2 ? bm : bn) + row) * K + s * 32 + kch;
            CPA16(buf + tilei * 10240 + row * 80 + kch * 2, src);
        }
        asm volatile("cp.async.commit_group;");
    };

    float acc[4][4][4];
    #pragma unroll
    for (int i = 0; i < 4; i++)
        #pragma unroll
        for (int j = 0; j < 4; j++)
            #pragma unroll
            for (int q = 0; q < 4; q++) acc[i][j][q] = 0.f;

    const int S = K >> 5;
    load_stage(0, 0);
    load_stage(1, 1);

    for (int s = 0; s < S; s++) {
        int b = s & 1;
        if (s >= S - 1) asm volatile("cp.async.wait_group 0;");
        else            asm volatile("cp.async.wait_group 1;");
        __syncthreads();
        uint32_t buf = sbase + b * GM_STAGE;
        #pragma unroll
        for (int ks = 0; ks < 2; ks++) {
            int k0 = ks * 16;
            uint32_t ah[4][4], al[4][4], bh[4][2], bl[4][2];
            int arow = wm + (lane & 15);
            int acol = (k0 + ((lane >> 4) & 1) * 8) * 2;
            #pragma unroll
            for (int mf = 0; mf < 4; mf++) {
                lm4(buf +         (arow + mf * 16) * 80 + acol, ah[mf]);
                lm4(buf + 10240 + (arow + mf * 16) * 80 + acol, al[mf]);
            }
            int l16 = lane & 15;
            int brow = wn + (l16 & 7);
            int bcol = (k0 + ((l16 >> 3) & 1) * 8) * 2;
            #pragma unroll
            for (int nf = 0; nf < 4; nf++) {
                lm2(buf + 20480 + (brow + nf * 8) * 80 + bcol, bh[nf]);
                lm2(buf + 30720 + (brow + nf * 8) * 80 + bcol, bl[nf]);
            }
            #pragma unroll
            for (int mf = 0; mf < 4; mf++)
                #pragma unroll
                for (int nf = 0; nf < 4; nf++) {
                    MMA(acc[mf][nf], ah[mf], bh[nf]);
                    MMA(acc[mf][nf], ah[mf], bl[nf]);
                    MMA(acc[mf][nf], al[mf], bh[nf]);
                }
        }
        __syncthreads();
        if (s + 2 < S) load_stage(s + 2, b);
    }

    #pragma unroll
    for (int mf = 0; mf < 4; mf++)
        #pragma unroll
        for (int nf = 0; nf < 4; nf++)
            #pragma unroll
            for (int half = 0; half < 2; half++) {
                int row = bm + wm + mf * 16 + (lane >> 2) + half * 8;
                int col = bn + wn + nf * 8 + 2 * (lane & 3);
                float2 v = make_float2(acc[mf][nf][half * 2], acc[mf][nf][half * 2 + 1]);
                float2 bv = *(const float2*)(bias + col);
                v.x += bv.x; v.y += bv.y;
                size_t gr = (size_t)row;
                if (mode == 2) {
                    float2 r = *(const float2*)(resid + gr * ldr + col);
                    v.x += r.x; v.y += r.y;
                }
                if (mode == 1 || mode == 3) {
                    if (mode == 1) { v.x = fmaxf(v.x, 0.f); v.y = fmaxf(v.y, 0.f); }
                    uint32_t lo, hi = packsplit(v.x, v.y, lo);
                    *(uint32_t*)(Chi + gr * ldc + col) = hi;
                    *(uint32_t*)(Clo + gr * ldc + col) = lo;
                } else {
                    *(float2*)(C + gr * ldc + col) = v;
                }
            }
}

// ============ fused flash attention (split-bf16 HMMA) ============
#define FA_QBY (128 * 104 * 2)
#define FA_KBY (64 * 104 * 2)
#define FA_STAGE (4 * FA_KBY)
#define FA_SMEM (2 * FA_QBY + 2 * FA_STAGE)

__global__ void __launch_bounds__(256, 1) flash_attn(int causal) {
    extern __shared__ char sm_[];
    const int tid = threadIdx.x, wid = tid >> 5, lane = tid & 31;
    const int qt = blockIdx.x, bh = blockIdx.y;
    const int b = bh >> 3, h = bh & 7;
    uint32_t sb = smem_u32(sm_);
    uint32_t sQh = sb, sQl = sb + FA_QBY;
    auto stK = [&](int st, int arr) { return sb + 2*FA_QBY + st*FA_STAGE + arr*FA_KBY; };
    const size_t rowb = (size_t)(b * Ss);

    // Q load (once).  BUGFIX: 1536 is NOT a power of two, so "c & 1535" was
    // wrong for c >= 1536 (left sQl partially uninitialized -> NaN).  Use
    // explicit subtraction.
    #pragma unroll
    for (int i = 0; i < 12; i++) {
        int c = tid + i * 256;
        int split = (c >= 1536) ? 1 : 0;
        int idx = c - split * 1536;
        int row = idx / 12, ch = idx % 12;
        const bf16* src = (split ? g_qkvl : g_qkvh) + (rowb + qt*128 + row)*(3*Dd) + h*DH + ch*8;
        CPA16((split ? sQl : sQh) + row*208 + ch*16, src);
    }
    asm volatile("cp.async.commit_group;");

    auto loadKV = [&](int kt, int st) {
        #pragma unroll
        for (int i = 0; i < 12; i++) {
            int c = tid + i * 256;
            int arr = c / 768, idx = c % 768;
            int row = idx / 12, ch = idx % 12;
            const bf16* base = (arr & 1) ? g_qkvl : g_qkvh;
            int off = (arr < 2) ? Dd : 2 * Dd;
            CPA16(stK(st, arr) + row*208 + ch*16,
                  base + (rowb + kt*64 + row)*(3*Dd) + off + h*DH + ch*8);
        }
        asm volatile("cp.async.commit_group;");
    };
    loadKV(0, 0);
    loadKV(1, 1);
    asm volatile("cp.async.wait_group 1;");
    __syncthreads();

    // preload Q A-frags
    uint32_t qAh[6][4], qAl[6][4];
    {
        int arow = wid*16 + (lane & 15);
        #pragma unroll
        for (int j = 0; j < 6; j++) {
            int acol = (j*16 + ((lane >> 4) & 1) * 8) * 2;
            lm4(sQh + arow*208 + acol, qAh[j]);
            lm4(sQl + arow*208 + acol, qAl[j]);
        }
    }

    float O[12][4];
    #pragma unroll
    for (int nv = 0; nv < 12; nv++)
        #pragma unroll
        for (int q = 0; q < 4; q++) O[nv][q] = 0.f;
    float m0 = -3.4e38f, m1 = -3.4e38f, l0 = 0.f, l1 = 0.f;
    const int qr0 = qt*128 + wid*16 + (lane >> 2);
    const int l16 = lane & 15;
    const float isc = 0.10206207261596577f;  // 1/sqrt(96)

    for (int kt = 0; kt < 8; kt++) {
        int st = kt & 1;
        // tail: at last iteration only the needed group remains in flight
        if (kt >= 7) asm volatile("cp.async.wait_group 0;");
        else         asm volatile("cp.async.wait_group 1;");
        __syncthreads();

        // scores S = Q @ K^T (3-split)
        float S[8][4];
        #pragma unroll
        for (int nt = 0; nt < 8; nt++) { S[nt][0]=S[nt][1]=S[nt][2]=S[nt][3]=0.f; }
        uint32_t kb0 = stK(st, 0), kb1 = stK(st, 1);
        #pragma unroll
        for (int nt = 0; nt < 8; nt++) {
            uint32_t ba = (uint32_t)((nt*8 + (l16 & 7))*208 + (l16 >> 3)*16);
            #pragma unroll
            for (int j = 0; j < 6; j++) {
                uint32_t bhf[2], blf[2];
                lm2(kb0 + ba + j*32, bhf);
                lm2(kb1 + ba + j*32, blf);
                MMA(S[nt], qAh[j], bhf);
                MMA(S[nt], qAh[j], blf);
                MMA(S[nt], qAl[j], bhf);
            }
        }
        // mask + online softmax
        float mx0 = -3.4e38f, mx1 = -3.4e38f;
        #pragma unroll
        for (int nt = 0; nt < 8; nt++) {
            int k0 = kt*64 + nt*8 + 2*(lane & 3);
            float pd0 = g_padf[b*Ss + k0], pd1 = g_padf[b*Ss + k0 + 1];
            float s0 = S[nt][0]*isc + pd0 + ((causal && qr0 > k0)     ? NEGB : 0.f);
            float s1 = S[nt][1]*isc + pd1 + ((causal && qr0 > k0 + 1) ? NEGB : 0.f);
            float s2 = S[nt][2]*isc + pd0 + ((causal && qr0+8 > k0)   ? NEGB : 0.f);
            float s3 = S[nt][3]*isc + pd1 + ((causal && qr0+8 > k0+1) ? NEGB : 0.f);
            S[nt][0]=s0; S[nt][1]=s1; S[nt][2]=s2; S[nt][3]=s3;
            mx0 = fmaxf(mx0, fmaxf(s0, s1));
            mx1 = fmaxf(mx1, fmaxf(s2, s3));
        }
        mx0 = fmaxf(mx0, __shfl_xor_sync(0xffffffffu, mx0, 1));
        mx0 = fmaxf(mx0, __shfl_xor_sync(0xffffffffu, mx0, 2));
        mx1 = fmaxf(mx1, __shfl_xor_sync(0xffffffffu, mx1, 1));
        mx1 = fmaxf(mx1, __shfl_xor_sync(0xffffffffu, mx1, 2));
        float mn0 = fmaxf(m0, mx0), mn1 = fmaxf(m1, mx1);
        float cr0 = __expf(m0 - mn0), cr1 = __expf(m1 - mn1);
        m0 = mn0; m1 = mn1;
        l0 *= cr0; l1 *= cr1;
        #pragma unroll
        for (int nv = 0; nv < 12; nv++) {
            O[nv][0] *= cr0; O[nv][1] *= cr0; O[nv][2] *= cr1; O[nv][3] *= cr1;
        }
        #pragma unroll
        for (int nt = 0; nt < 8; nt++) {
            S[nt][0] = __expf(S[nt][0] - mn0); S[nt][1] = __expf(S[nt][1] - mn0);
            S[nt][2] = __expf(S[nt][2] - mn1); S[nt][3] = __expf(S[nt][3] - mn1);
            l0 += S[nt][0] + S[nt][1];
            l1 += S[nt][2] + S[nt][3];
        }
        // pack P into A-frags
        uint32_t pAh[4][4], pAl[4][4];
        #pragma unroll
        for (int js = 0; js < 4; js++) {
            int a = 2*js, c = 2*js + 1;
            pAh[js][0] = packsplit(S[a][0], S[a][1], pAl[js][0]);
            pAh[js][1] = packsplit(S[a][2], S[a][3], pAl[js][1]);
            pAh[js][2] = packsplit(S[c][0], S[c][1], pAl[js][2]);
            pAh[js][3] = packsplit(S[c][2], S[c][3], pAl[js][3]);
        }
        // O += P @ V (3-split, V^T via ldmatrix.trans)
        uint32_t vb0 = stK(st, 2), vb1 = stK(st, 3);
        #pragma unroll
        for (int nv = 0; nv < 12; nv++) {
            #pragma unroll
            for (int js = 0; js < 4; js++) {
                uint32_t bhf[2], blf[2];
                uint32_t va = (uint32_t)((js*16 + l16)*208 + nv*16);
                lm2t(vb0 + va, bhf);
                lm2t(vb1 + va, blf);
                MMA(O[nv], pAh[js], bhf);
                MMA(O[nv], pAh[js], blf);
                MMA(O[nv], pAl[js], bhf);
            }
        }
        __syncthreads();
        if (kt + 2 < 8) loadKV(kt + 2, st);
    }

    l0 += __shfl_xor_sync(0xffffffffu, l0, 1);
    l0 += __shfl_xor_sync(0xffffffffu, l0, 2);
    l1 += __shfl_xor_sync(0xffffffffu, l1, 1);
    l1 += __shfl_xor_sync(0xffffffffu, l1, 2);
    float i0 = 1.f / l0, i1 = 1.f / l1;
    size_t gr0 = rowb + (size_t)qr0;
    size_t gr1 = gr0 + 8;
    int colb = h*DH + 2*(lane & 3);
    #pragma unroll
    for (int nv = 0; nv < 12; nv++) {
        uint32_t lo, hi;
        hi = packsplit(O[nv][0]*i0, O[nv][1]*i0, lo);
        *(uint32_t*)(g_att_h + gr0*Dd + colb + nv*8) = hi;
        *(uint32_t*)(g_att_l + gr0*Dd + colb + nv*8) = lo;
        hi = packsplit(O[nv][2]*i1, O[nv][3]*i1, lo);
        *(uint32_t*)(g_att_h + gr1*Dd + colb + nv*8) = hi;
        *(uint32_t*)(g_att_l + gr1*Dd + colb + nv*8) = lo;
    }
}

// ---------------- reductions ----------------
__device__ __forceinline__ float bsum(float v, float* sb) {
    int tid = threadIdx.x;
    #pragma unroll
    for (int o = 16; o > 0; o >>= 1) v += __shfl_down_sync(0xffffffffu, v, o);
    if ((tid & 31) == 0) sb[tid >> 5] = v;
    __syncthreads();
    float s = 0.f;
    if (tid < 32) {
        s = (tid < (int)(blockDim.x >> 5)) ? sb[tid] : 0.f;
        #pragma unroll
        for (int o = 16; o > 0; o >>= 1) s += __shfl_down_sync(0xffffffffu, s, o);
        if (tid == 0) sb[0] = s;
    }
    __syncthreads();
    float r = sb[0]; __syncthreads(); return r;
}

// ---------------- small kernels ----------------
__global__ void __launch_bounds__(256) cvt_split(const float* __restrict__ x,
                                                 bf16* __restrict__ hi, bf16* __restrict__ lo, int n4) {
    int i = blockIdx.x * 256 + threadIdx.x;
    if (i >= n4) return;
    float4 v = ((const float4*)x)[i];
    uint32_t l01, h01 = packsplit(v.x, v.y, l01);
    uint32_t l23, h23 = packsplit(v.z, v.w, l23);
    ((uint2*)hi)[i] = make_uint2(h01, h23);
    ((uint2*)lo)[i] = make_uint2(l01, l23);
}

__global__ void __launch_bounds__(256) rowstat_x(const float* __restrict__ x) {
    __shared__ float sb[32];
    int row = blockIdx.x, tid = threadIdx.x;
    float v[3];
    #pragma unroll
    for (int i = 0; i < 3; i++) v[i] = x[(size_t)row * Dd + tid + i * 256];
    float ss = bsum(v[0]*v[0] + v[1]*v[1] + v[2]*v[2], sb);
    int pad = (sqrtf(ss) <= 1e-6f) ? 1 : 0;
    if (tid == 0) { g_pad[row] = pad; g_xnorm[row] = pad ? 0.f : ss; g_padf[row] = pad ? NEGB : 0.f; }
    #pragma unroll
    for (int i = 0; i < 3; i++) {
        int c = tid + i * 256;
        float o = pad ? 0.f : v[i];
        g_mem[(size_t)row * Dd + c] = o;
        bf16 hh, ll; split2(o, hh, ll);
        g_mem_h[(size_t)row * Dd + c] = hh;
        g_mem_l[(size_t)row * Dd + c] = ll;
    }
}
__global__ void __launch_bounds__(256) rowstat_cb(const float* __restrict__ cb) {
    __shared__ float sb[32];
    int row = blockIdx.x, tid = threadIdx.x;
    float ss = 0.f;
    #pragma unroll
    for (int i = 0; i < 3; i++) { float v = cb[(size_t)row * Dd + tid + i * 256]; ss += v * v; }
    ss = bsum(ss, sb);
    if (tid == 0) g_cnorm[row] = ss;
}

// ---------------- fp32 NT SGEMM (VQ distances, exact) ----------------
__global__ void __launch_bounds__(256) sgemm_nt(
    const float* __restrict__ A, const float* __restrict__ W,
    const float* __restrict__ rnorm, const float* __restrict__ cnorm,
    float* __restrict__ C, int ldc, int K)
{
    __shared__ float As[16][132];
    __shared__ float Ws[16][132];
    const int bm = blockIdx.y * 128, bn = blockIdx.x * 128;
    const int tid = threadIdx.x, tx = tid & 15, ty = tid >> 4;
    float acc[8][8];
    #pragma unroll
    for (int i = 0; i < 8; i++)
        #pragma unroll
        for (int j = 0; j < 8; j++) acc[i][j] = 0.f;
    for (int k0 = 0; k0 < K; k0 += 16) {
        #pragma unroll
        for (int u = 0; u < 2; u++) {
            int f = tid + u * 256;
            int row = f >> 2, c4 = (f & 3) << 2;
            float4 a = *(const float4*)(A + (size_t)(bm + row) * K + k0 + c4);
            As[c4+0][row]=a.x; As[c4+1][row]=a.y; As[c4+2][row]=a.z; As[c4+3][row]=a.w;
            float4 w = *(const float4*)(W + (size_t)(bn + row) * K + k0 + c4);
            Ws[c4+0][row]=w.x; Ws[c4+1][row]=w.y; Ws[c4+2][row]=w.z; Ws[c4+3][row]=w.w;
        }
        __syncthreads();
        #pragma unroll
        for (int kk = 0; kk < 16; kk++) {
            float a[8], b[8];
            *(float4*)(a)   = *(const float4*)&As[kk][ty*8];
            *(float4*)(a+4) = *(const float4*)&As[kk][ty*8+4];
            *(float4*)(b)   = *(const float4*)&Ws[kk][tx*8];
            *(float4*)(b+4) = *(const float4*)&Ws[kk][tx*8+4];
            #pragma unroll
            for (int i = 0; i < 8; i++)
                #pragma unroll
                for (int j = 0; j < 8; j++) acc[i][j] = fmaf(a[i], b[j], acc[i][j]);
        }
        __syncthreads();
    }
    #pragma unroll
    for (int i = 0; i < 8; i++) {
        int row = bm + ty * 8 + i;
        float xn = rnorm[row];
        #pragma unroll
        for (int jj = 0; jj < 8; jj += 4) {
            int col = bn + tx * 8 + jj;
            float4 v;
            v.x = (xn + cnorm[col+0]) - 2.f*acc[i][jj];
            v.y = (xn + cnorm[col+1]) - 2.f*acc[i][jj+1];
            v.z = (xn + cnorm[col+2]) - 2.f*acc[i][jj+2];
            v.w = (xn + cnorm[col+3]) - 2.f*acc[i][jj+3];
            *(float4*)(C + (size_t)row * ldc + col) = v;
        }
    }
}

// ---------------- layernorm (+split) ----------------
__global__ void __launch_bounds__(256) layernorm(const float* __restrict__ gam,
                                                 const float* __restrict__ bet) {
    __shared__ float sb[32];
    int row = blockIdx.x, tid = threadIdx.x;
    const float* x = g_tmp + (size_t)row * Dd;
    float v[3];
    #pragma unroll
    for (int i = 0; i < 3; i++) v[i] = x[tid + i * 256];
    float s = bsum(v[0] + v[1] + v[2], sb);
    float mean = s / 768.0f;
    float d2 = 0.f;
    #pragma unroll
    for (int i = 0; i < 3; i++) { float d = v[i] - mean; d2 += d * d; }
    d2 = bsum(d2, sb);
    float inv = 1.0f / sqrtf(d2 / 768.0f + 1e-5f);
    #pragma unroll
    for (int i = 0; i < 3; i++) {
        int c = tid + i * 256;
        float o = (v[i] - mean) * inv * gam[c] + bet[c];
        g_h[(size_t)row * Dd + c] = o;
        bf16 hh, ll; split2(o, hh, ll);
        g_h_h[(size_t)row * Dd + c] = hh;
        g_h_l[(size_t)row * Dd + c] = ll;
    }
}

// ---------------- threefry (JAX-exact) ----------------
__device__ __forceinline__ uint32_t rotl32(uint32_t x, int d) { return (x << d) | (x >> (32 - d)); }
__device__ void threefry2x32(uint32_t k0, uint32_t k1, uint32_t x0, uint32_t x1,
                             uint32_t& o0, uint32_t& o1) {
    uint32_t k2 = k0 ^ k1 ^ 0x1BD11BDAu;
    x0 += k0; x1 += k1;
    x0+=x1; x1=rotl32(x1,13); x1^=x0;  x0+=x1; x1=rotl32(x1,15); x1^=x0;
    x0+=x1; x1=rotl32(x1,26); x1^=x0;  x0+=x1; x1=rotl32(x1,6);  x1^=x0;
    x0 += k1; x1 += k2 + 1u;
    x0+=x1; x1=rotl32(x1,17); x1^=x0;  x0+=x1; x1=rotl32(x1,29); x1^=x0;
    x0+=x1; x1=rotl32(x1,16); x1^=x0;  x0+=x1; x1=rotl32(x1,24); x1^=x0;
    x0 += k2; x1 += k0 + 2u;
    x0+=x1; x1=rotl32(x1,13); x1^=x0;  x0+=x1; x1=rotl32(x1,15); x1^=x0;
    x0+=x1; x1=rotl32(x1,26); x1^=x0;  x0+=x1; x1=rotl32(x1,6);  x1^=x0;
    x0 += k0; x1 += k1 + 3u;
    x0+=x1; x1=rotl32(x1,17); x1^=x0;  x0+=x1; x1=rotl32(x1,29); x1^=x0;
    x0+=x1; x1=rotl32(x1,16); x1^=x0;  x0+=x1; x1=rotl32(x1,24); x1^=x0;
    x0 += k1; x1 += k2 + 4u;
    x0+=x1; x1=rotl32(x1,13); x1^=x0;  x0+=x1; x1=rotl32(x1,15); x1^=x0;
    x0+=x1; x1=rotl32(x1,26); x1^=x0;  x0+=x1; x1=rotl32(x1,6);  x1^=x0;
    x0 += k2; x1 += k0 + 5u;
    o0 = x0; o1 = x1;
}

// ---------------- VQ top-10 + gumbel ----------------
__global__ void __launch_bounds__(256) vq_topk_sample() {
    int row = blockIdx.x, tid = threadIdx.x;
    const float* __restrict__ drow = g_dist + (size_t)row * Kc;
    float td[10]; int ti[10];
    #pragma unroll
    for (int j = 0; j < 10; j++) { td[j] = 3.4e38f; ti[j] = 0x7fffffff; }
    for (int c = tid; c < Kc; c += 256) {
        float v = drow[c];
        if (v < td[9] || (v == td[9] && c < ti[9])) {
            int pos = 9;
            #pragma unroll
            for (int j = 8; j >= 0; j--) {
                bool lt = (v < td[j]) || (v == td[j] && c < ti[j]);
                if (lt) pos = j;
            }
            #pragma unroll
            for (int j = 9; j > 0; j--)
                if (j > pos) { td[j] = td[j-1]; ti[j] = ti[j-1]; }
            td[pos] = v; ti[pos] = c;
        }
    }
    __shared__ float sd[2560];
    __shared__ int   si[2560];
    #pragma unroll
    for (int j = 0; j < 10; j++) { sd[tid*10+j] = td[j]; si[tid*10+j] = ti[j]; }
    for (int stride = 128; stride >= 1; stride >>= 1) {
        __syncthreads();
        if (tid < stride) {
            float od[10]; int oi[10];
            int a = 0, b2 = 0;
            #pragma unroll
            for (int j = 0; j < 10; j++) {
                float da = sd[tid*10+a], db = sd[(tid+stride)*10+b2];
                int   ia = si[tid*10+a], ib = si[(tid+stride)*10+b2];
                bool ta = (da < db) || (da == db && ia <= ib);
                if (ta) { od[j]=da; oi[j]=ia; a++; } else { od[j]=db; oi[j]=ib; b2++; }
            }
            #pragma unroll
            for (int j = 0; j < 10; j++) { sd[tid*10+j]=od[j]; si[tid*10+j]=oi[j]; }
        }
    }
    __syncthreads();
    if (tid == 0) {
        float best = -3.4e38f;
        int bi = si[0];
        for (int j = 0; j < 10; j++) {
            uint32_t e = (uint32_t)(row * 10 + j);
            uint32_t o0, o1;
            threefry2x32(0u, 42u, 0u, e, o0, o1);
            uint32_t bits = o0 ^ o1;
            float u = __uint_as_float((bits >> 9) | 0x3f800000u) - 1.0f;
            u = fmaxf(1e-10f, u + 1e-10f);
            float gmb = -logf(-logf(u));
            float sc = -sd[j] + gmb;
            if (sc > best) { best = sc; bi = si[j]; }
        }
        g_enc[row] = bi;
    }
}

__global__ void __launch_bounds__(256) vq_quantize(const float* __restrict__ cb) {
    int row = blockIdx.x, tid = threadIdx.x;
    int e = g_enc[row];
    #pragma unroll
    for (int i = 0; i < 3; i++) {
        int c = tid + i * 256;
        float z = g_mem[(size_t)row * Dd + c];
        float q = cb[(size_t)e * Dd + c];
        float o = z + (q - z);
        g_h[(size_t)row * Dd + c] = o;
        bf16 hh, ll; split2(o, hh, ll);
        g_h_h[(size_t)row * Dd + c] = hh;
        g_h_l[(size_t)row * Dd + c] = ll;
    }
}

// ---------------- host ----------------
static void* sym(const void* s) { void* p = nullptr; cudaGetSymbolAddress(&p, s); return p; }

extern "C" void kernel_launch(void* const* d_in, const int* in_sizes, int n_in,
                              void* d_out, int out_size) {
    const float* x     = (const float*)d_in[0];
    const float* cb    = (const float*)d_in[1];
    const float* sib   = (const float*)d_in[3];
    const float* sob   = (const float*)d_in[5];
    const float* cib   = (const float*)d_in[7];
    const float* cob   = (const float*)d_in[9];
    const float* ln1g  = (const float*)d_in[10];
    const float* ln1b  = (const float*)d_in[11];
    const float* ln2g  = (const float*)d_in[12];
    const float* ln2b  = (const float*)d_in[13];
    const float* ln3g  = (const float*)d_in[14];
    const float* ln3b  = (const float*)d_in[15];
    const float* fb1   = (const float*)d_in[17];
    const float* fb2   = (const float*)d_in[19];
    const float* outb  = (const float*)d_in[21];
    float* outp = (float*)d_out;

    cudaFuncSetAttribute(gemm_mma, cudaFuncAttributeMaxDynamicSharedMemorySize, GM_SMEM);
    cudaFuncSetAttribute(flash_attn, cudaFuncAttributeMaxDynamicSharedMemorySize, FA_SMEM);

    float* p_mem  = (float*)sym(g_mem);
    float* p_h    = (float*)sym(g_h);
    float* p_tmp  = (float*)sym(g_tmp);
    float* p_dist = (float*)sym(g_dist);
    float* p_xn   = (float*)sym(g_xnorm);
    float* p_cn   = (float*)sym(g_cnorm);
    bf16 *qkh = (bf16*)sym(g_qkvh), *qkl = (bf16*)sym(g_qkvl);
    bf16 *hh = (bf16*)sym(g_h_h),   *hl = (bf16*)sym(g_h_l);
    bf16 *ah = (bf16*)sym(g_att_h), *al = (bf16*)sym(g_att_l);
    bf16 *mh = (bf16*)sym(g_mem_h), *ml = (bf16*)sym(g_mem_l);
    bf16 *fh = (bf16*)sym(g_ff_h),  *fl = (bf16*)sym(g_ff_l);
    bf16 *wsa_h = (bf16*)sym(g_wsain_h),  *wsa_l = (bf16*)sym(g_wsain_l);
    bf16 *wso_h = (bf16*)sym(g_wsaout_h), *wso_l = (bf16*)sym(g_wsaout_l);
    bf16 *wca_h = (bf16*)sym(g_wcain_h),  *wca_l = (bf16*)sym(g_wcain_l);
    bf16 *wco_h = (bf16*)sym(g_wcaout_h), *wco_l = (bf16*)sym(g_wcaout_l);
    bf16 *wf1_h = (bf16*)sym(g_wff1_h),   *wf1_l = (bf16*)sym(g_wff1_l);
    bf16 *wf2_h = (bf16*)sym(g_wff2_h),   *wf2_l = (bf16*)sym(g_wff2_l);
    bf16 *wo_h  = (bf16*)sym(g_wout_h),   *wo_l  = (bf16*)sym(g_wout_l);

    auto CVT = [](const float* s, bf16* h, bf16* l, size_t n) {
        int n4 = (int)(n / 4);
        cvt_split<<<(n4 + 255) / 256, 256>>>(s, h, l, n4);
    };
    auto TG = [&](const bf16* Ah, const bf16* Al, const bf16* Wh, const bf16* Wl,
                  const float* bias, const float* resid, float* C, bf16* Ch, bf16* Cl,
                  int ldc, int N, int K, int mode) {
        dim3 grid(N / 128, NTOK / 128);
        gemm_mma<<<grid, 256, GM_SMEM>>>(Ah, Al, Wh, Wl, bias, resid, Dd, C, Ch, Cl, ldc, K, mode);
    };

    CVT((const float*)d_in[2],  wsa_h, wsa_l, (size_t)W_SAIN_N);
    CVT((const float*)d_in[4],  wso_h, wso_l, (size_t)W_SQ_N);
    CVT((const float*)d_in[6],  wca_h, wca_l, (size_t)W_SAIN_N);
    CVT((const float*)d_in[8],  wco_h, wco_l, (size_t)W_SQ_N);
    CVT((const float*)d_in[16], wf1_h, wf1_l, (size_t)W_FF1_N);
    CVT((const float*)d_in[18], wf2_h, wf2_l, (size_t)W_FF2_N);
    CVT((const float*)d_in[20], wo_h,  wo_l,  (size_t)W_OUT_N);

    // VQ (fp32 exact)
    rowstat_x<<<NTOK, 256>>>(x);
    rowstat_cb<<<Kc, 256>>>(cb);
    {
        dim3 grid(Kc / 128, NTOK / 128);
        sgemm_nt<<<grid, 256>>>(p_mem, cb, p_xn, p_cn, p_dist, Kc, Dd);
    }
    vq_topk_sample<<<NTOK, 256>>>();
    vq_quantize<<<NTOK, 256>>>(cb);

    for (int l = 0; l < Ll; l++) {
        size_t win = (size_t)l * 3 * Dd * Dd, wsq = (size_t)l * Dd * Dd;
        // self-attention
        TG(hh, hl, wsa_h + win, wsa_l + win, sib + (size_t)l*3*Dd, nullptr,
           nullptr, qkh, qkl, 3*Dd, 3*Dd, Dd, 3);
        flash_attn<<<dim3(4, Bb*Hh), 256, FA_SMEM>>>(1);
        TG(ah, al, wso_h + wsq, wso_l + wsq, sob + (size_t)l*Dd, p_h,
           p_tmp, nullptr, nullptr, Dd, Dd, Dd, 2);
        layernorm<<<NTOK, 256>>>(ln1g + (size_t)l*Dd, ln1b + (size_t)l*Dd);

        // cross-attention
        TG(hh, hl, wca_h + win, wca_l + win, cib + (size_t)l*3*Dd, nullptr,
           nullptr, qkh, qkl, 3*Dd, Dd, Dd, 3);
        TG(mh, ml, wca_h + win + (size_t)Dd*Dd, wca_l + win + (size_t)Dd*Dd,
           cib + (size_t)l*3*Dd + Dd, nullptr,
           nullptr, qkh + Dd, qkl + Dd, 3*Dd, 2*Dd, Dd, 3);
        flash_attn<<<dim3(4, Bb*Hh), 256, FA_SMEM>>>(0);
        TG(ah, al, wco_h + wsq, wco_l + wsq, cob + (size_t)l*Dd, p_h,
           p_tmp, nullptr, nullptr, Dd, Dd, Dd, 2);
        layernorm<<<NTOK, 256>>>(ln2g + (size_t)l*Dd, ln2b + (size_t)l*Dd);

        // feed-forward
        TG(hh, hl, wf1_h + (size_t)l*FFd*Dd, wf1_l + (size_t)l*FFd*Dd,
           fb1 + (size_t)l*FFd, nullptr, nullptr, fh, fl, FFd, FFd, Dd, 1);
        TG(fh, fl, wf2_h + (size_t)l*Dd*FFd, wf2_l + (size_t)l*Dd*FFd,
           fb2 + (size_t)l*Dd, p_h, p_tmp, nullptr, nullptr, Dd, Dd, FFd, 2);
        layernorm<<<NTOK, 256>>>(ln3g + (size_t)l*Dd, ln3b + (size_t)l*Dd);
    }

    TG(hh, hl, wo_h, wo_l, outb, nullptr, outp, nullptr, nullptr, Dd, Dd, Dd, 0);
}